// round 12
// baseline (speedup 1.0000x reference)
#include <cuda_runtime.h>
#include <cuda_bf16.h>
#include <math.h>
#include <stdint.h>
#include <string.h>

#define BATCH 4
#define CIN   256
#define HW    4096
#define DIM   64
#define LOG2E 1.4426950408889634f

typedef unsigned int u32;
typedef unsigned long long u64;

// ---------------------------------------------------------------------------
// Device scratch
// ---------------------------------------------------------------------------
__device__ __nv_bfloat16 g_xth[BATCH * HW * CIN];   // x transposed [b][n][c] hi
__device__ __nv_bfloat16 g_xtl[BATCH * HW * CIN];   // lo
__device__ __nv_bfloat16 g_wh[3 * DIM * CIN];       // wq|wk|wv hi
__device__ __nv_bfloat16 g_wl[3 * DIM * CIN];
__device__ __nv_bfloat16 g_wsah[CIN * DIM];
__device__ __nv_bfloat16 g_wsal[CIN * DIM];
__device__ __nv_bfloat16 g_qh[BATCH * HW * DIM];    // q pre-scaled by log2(e)
__device__ __nv_bfloat16 g_ql[BATCH * HW * DIM];
__device__ __nv_bfloat16 g_kh[BATCH * HW * DIM];
__device__ __nv_bfloat16 g_kl[BATCH * HW * DIM];
__device__ __nv_bfloat16 g_vth[BATCH * DIM * HW];   // [b][d][j] (hi only)
__device__ __nv_bfloat16 g_sah[BATCH * HW * DIM];   // attention out [b][n][d]
__device__ __nv_bfloat16 g_sal[BATCH * HW * DIM];

// ---------------------------------------------------------------------------
// Helpers
// ---------------------------------------------------------------------------
__device__ __forceinline__ uint32_t smem_u32(const void* p) {
    uint32_t a;
    asm("{ .reg .u64 t; cvta.to.shared.u64 t, %1; cvt.u32.u64 %0, t; }" : "=r"(a) : "l"(p));
    return a;
}
// pack two floats into bf16x2: lo -> bits[15:0], hi -> bits[31:16]
__device__ __forceinline__ u32 packbf(float lo, float hi) {
    u32 r;
    asm("cvt.rn.bf16x2.f32 %0, %1, %2;" : "=r"(r) : "f"(hi), "f"(lo));
    return r;
}
__device__ __forceinline__ float2 unpackbf(u32 u) {
    __nv_bfloat162 h;
    memcpy(&h, &u, 4);
    return make_float2(__bfloat162float(h.x), __bfloat162float(h.y));
}
__device__ __forceinline__ float ex2f(float x) {
    float r;
    asm("ex2.approx.f32 %0, %1;" : "=f"(r) : "f"(x));
    return r;
}
__device__ __forceinline__ void mma16816(float* c, const u32* a, const u32* b) {
    asm volatile(
        "mma.sync.aligned.m16n8k16.row.col.f32.bf16.bf16.f32 "
        "{%0,%1,%2,%3}, {%4,%5,%6,%7}, {%8,%9}, {%0,%1,%2,%3};"
        : "+f"(c[0]), "+f"(c[1]), "+f"(c[2]), "+f"(c[3])
        : "r"(a[0]), "r"(a[1]), "r"(a[2]), "r"(a[3]), "r"(b[0]), "r"(b[1]));
}
__device__ __forceinline__ void ldsm4(u32* r, uint32_t addr) {
    asm volatile("ldmatrix.sync.aligned.m8n8.x4.shared.b16 {%0,%1,%2,%3}, [%4];"
        : "=r"(r[0]), "=r"(r[1]), "=r"(r[2]), "=r"(r[3]) : "r"(addr));
}
__device__ __forceinline__ void ldsm2(u32* r, uint32_t addr) {
    asm volatile("ldmatrix.sync.aligned.m8n8.x2.shared.b16 {%0,%1}, [%2];"
        : "=r"(r[0]), "=r"(r[1]) : "r"(addr));
}
#define CP16(dst, src) asm volatile("cp.async.cg.shared.global [%0], [%1], 16;" :: "r"(dst), "l"(src))
#define CPC()  asm volatile("cp.async.commit_group;")
#define CPW0() asm volatile("cp.async.wait_group 0;")

// XOR swizzles for 128B / 256B / 512B rows (16B granules)
__device__ __forceinline__ u32 swz128(u32 row, u32 g) { return row * 128u + ((g ^ (row & 7u)) << 4); }
__device__ __forceinline__ u32 swz256(u32 row, u32 g) { return row * 256u + (((g & 8u) | ((g & 7u) ^ (row & 7u))) << 4); }
__device__ __forceinline__ u32 swz512(u32 row, u32 g) { return row * 512u + (((g & 24u) | ((g & 7u) ^ (row & 7u))) << 4); }

// ---------------------------------------------------------------------------
// Kernel 0a: x [b][c][n] fp32 -> xt hi/lo [b][n][c] bf16 (tile transpose)
// ---------------------------------------------------------------------------
__global__ __launch_bounds__(256) void convert_x_kernel(const float* __restrict__ x)
{
    __shared__ float xs[64][65];
    const int b  = blockIdx.z;
    const int c0 = blockIdx.y * 64;
    const int n0 = blockIdx.x * 64;
    const int tid = threadIdx.x;

#pragma unroll
    for (int i = 0; i < 4; i++) {
        int r = (tid >> 4) + i * 16;
        int col4 = (tid & 15) * 4;
        float4 v = *(const float4*)&x[(size_t)(b * CIN + c0 + r) * HW + n0 + col4];
        xs[r][col4 + 0] = v.x;
        xs[r][col4 + 1] = v.y;
        xs[r][col4 + 2] = v.z;
        xs[r][col4 + 3] = v.w;
    }
    __syncthreads();

    const int n  = tid >> 2;
    const int cs = (tid & 3) * 16;
    u32 hh[8], ll[8];
#pragma unroll
    for (int j = 0; j < 16; j += 2) {
        float a = xs[cs + j][n];
        float b2 = xs[cs + j + 1][n];
        u32 h = packbf(a, b2);
        float2 f = unpackbf(h);
        hh[j >> 1] = h;
        ll[j >> 1] = packbf(a - f.x, b2 - f.y);
    }
    size_t base = ((size_t)(b * HW) + n0 + n) * CIN + c0 + cs;
    *(uint4*)&g_xth[base]     = *(uint4*)&hh[0];
    *(uint4*)&g_xth[base + 8] = *(uint4*)&hh[4];
    *(uint4*)&g_xtl[base]     = *(uint4*)&ll[0];
    *(uint4*)&g_xtl[base + 8] = *(uint4*)&ll[4];
}

// ---------------------------------------------------------------------------
// Kernel 0b: weight conversion -> bf16 hi/lo
// ---------------------------------------------------------------------------
__global__ void convert_w_kernel(const float* __restrict__ wq, const float* __restrict__ wk,
                                 const float* __restrict__ wv, const float* __restrict__ wsa)
{
    const int p = blockIdx.x;
    const float* s = (p == 0) ? wq : (p == 1) ? wk : (p == 2) ? wv : wsa;
    __nv_bfloat16* dh = (p < 3) ? &g_wh[p * DIM * CIN] : g_wsah;
    __nv_bfloat16* dl = (p < 3) ? &g_wl[p * DIM * CIN] : g_wsal;
    for (int i = threadIdx.x; i < DIM * CIN; i += blockDim.x) {
        float v = s[i];
        __nv_bfloat16 h = __float2bfloat16(v);
        dh[i] = h;
        dl[i] = __float2bfloat16(v - __bfloat162float(h));
    }
}

// ---------------------------------------------------------------------------
// Kernel 1: QKV projections via HMMA hi/lo.
// out[n][d] = xt[n][c] . w[d][c]^T + bias.  M=128 (n), N=64 (d), K=256.
// q output pre-scaled by log2(e) so attention uses raw ex2.
// ---------------------------------------------------------------------------
#define QKV_SMEM 196608

__global__ __launch_bounds__(256, 1) void qkv_mma_kernel(
    const float* __restrict__ bq, const float* __restrict__ bk, const float* __restrict__ bv)
{
    extern __shared__ char sm[];
    const u32 sb = smem_u32(sm);
    const int tid  = threadIdx.x;
    const int lane = tid & 31;
    const int wid  = tid >> 5;
    const int wm = wid & 3;
    const int wn = wid >> 2;
    const int g  = lane >> 2;
    const int t  = lane & 3;
    const int b  = blockIdx.y;
    const int p  = blockIdx.z;
    const int i0 = blockIdx.x * 128;
    const float* bias = (p == 0) ? bq : (p == 1) ? bk : bv;
    const float scl = (p == 0) ? LOG2E : 1.0f;

    {
        const char* ah = (const char*)&g_xth[(size_t)(b * HW + i0) * CIN];
        const char* al = (const char*)&g_xtl[(size_t)(b * HW + i0) * CIN];
#pragma unroll
        for (int i = 0; i < 16; i++) {
            int id = tid + i * 256;
            u32 row = (u32)(id >> 5), gg = (u32)(id & 31);
            u32 o = swz512(row, gg);
            u32 so = row * 512 + gg * 16;
            CP16(sb + o, ah + so);
            CP16(sb + 65536 + o, al + so);
        }
        const char* bh = (const char*)&g_wh[p * DIM * CIN];
        const char* bl = (const char*)&g_wl[p * DIM * CIN];
#pragma unroll
        for (int i = 0; i < 8; i++) {
            int id = tid + i * 256;
            u32 row = (u32)(id >> 5), gg = (u32)(id & 31);
            u32 o = swz512(row, gg);
            u32 so = row * 512 + gg * 16;
            CP16(sb + 131072 + o, bh + so);
            CP16(sb + 163840 + o, bl + so);
        }
        CPC(); CPW0();
        __syncthreads();
    }

    float c[2][4][4];
#pragma unroll
    for (int mt = 0; mt < 2; mt++)
#pragma unroll
        for (int nt = 0; nt < 4; nt++)
#pragma unroll
            for (int e = 0; e < 4; e++) c[mt][nt][e] = 0.0f;

    const u32 a_row = wm * 32 + (lane & 15);
    const u32 a_g = (u32)(lane >> 4);
    const u32 b_row = wn * 32 + (lane & 7);
    const u32 b_g = (u32)((lane >> 3) & 1);

#pragma unroll
    for (int kt = 0; kt < 16; kt++) {
        u32 ah2[2][4], al2[2][4];
#pragma unroll
        for (int mt = 0; mt < 2; mt++) {
            u32 off = swz512(a_row + mt * 16, a_g + kt * 2);
            ldsm4(ah2[mt], sb + off);
            ldsm4(al2[mt], sb + 65536 + off);
        }
#pragma unroll
        for (int nt = 0; nt < 4; nt++) {
            u32 bh2[2], bl2[2];
            u32 off = swz512(b_row + nt * 8, b_g + kt * 2);
            ldsm2(bh2, sb + 131072 + off);
            ldsm2(bl2, sb + 163840 + off);
#pragma unroll
            for (int mt = 0; mt < 2; mt++) {
                mma16816(c[mt][nt], ah2[mt], bh2);
                mma16816(c[mt][nt], ah2[mt], bl2);
                mma16816(c[mt][nt], al2[mt], bh2);
            }
        }
    }

    if (p < 2) {
        __nv_bfloat16* oh = (p == 0) ? g_qh : g_kh;
        __nv_bfloat16* ol = (p == 0) ? g_ql : g_kl;
#pragma unroll
        for (int mt = 0; mt < 2; mt++)
#pragma unroll
            for (int nt = 0; nt < 4; nt++) {
                int n = i0 + wm * 32 + mt * 16 + g;
                int d = wn * 32 + nt * 8 + t * 2;
                float b0 = bias[d], b1 = bias[d + 1];
                float v0 = (c[mt][nt][0] + b0) * scl, v1 = (c[mt][nt][1] + b1) * scl;
                float v2 = (c[mt][nt][2] + b0) * scl, v3 = (c[mt][nt][3] + b1) * scl;
                u32 h01 = packbf(v0, v1); float2 f0 = unpackbf(h01);
                u32 l01 = packbf(v0 - f0.x, v1 - f0.y);
                u32 h23 = packbf(v2, v3); float2 f1 = unpackbf(h23);
                u32 l23 = packbf(v2 - f1.x, v3 - f1.y);
                size_t o0 = (size_t)(b * HW + n) * DIM + d;
                size_t o1 = (size_t)(b * HW + n + 8) * DIM + d;
                *(u32*)&oh[o0] = h01; *(u32*)&ol[o0] = l01;
                *(u32*)&oh[o1] = h23; *(u32*)&ol[o1] = l23;
            }
    } else {
        // v: bounce through smem, store hi only
        float* ot = (float*)sm;   // [64 d][128 n]
        __syncthreads();
#pragma unroll
        for (int mt = 0; mt < 2; mt++)
#pragma unroll
            for (int nt = 0; nt < 4; nt++) {
                int n = wm * 32 + mt * 16 + g;
                int d = wn * 32 + nt * 8 + t * 2;
                ot[d * 128 + n]           = c[mt][nt][0];
                ot[(d + 1) * 128 + n]     = c[mt][nt][1];
                ot[d * 128 + n + 8]       = c[mt][nt][2];
                ot[(d + 1) * 128 + n + 8] = c[mt][nt][3];
            }
        __syncthreads();
        int d  = tid >> 2;
        int ns = (tid & 3) * 32;
        float bvv = bias[d];
        u32 hh[16];
#pragma unroll
        for (int j = 0; j < 32; j += 2) {
            float v0 = ot[d * 128 + ns + j] + bvv;
            float v1 = ot[d * 128 + ns + j + 1] + bvv;
            hh[j >> 1] = packbf(v0, v1);
        }
        size_t base = (size_t)(b * DIM + d) * HW + i0 + ns;
#pragma unroll
        for (int q4 = 0; q4 < 4; q4++)
            *(uint4*)&g_vth[base + q4 * 8] = *(uint4*)&hh[q4 * 4];
    }
}

// ---------------------------------------------------------------------------
// Kernel 2: HMMA flash attention. BM=64, 256 threads = 8 warps (4 M-groups
// of 16 rows x 2 j-halves of 64). Q register-resident. 2 CTAs/SM to break
// the per-CTA phase lock (independent barriers de-phase tensor vs MUFU).
// Smem/CTA: Qh 0 (8K) | Ql 8K | buf0 16K..64K | buf1 64K..112K = 112KB.
// ---------------------------------------------------------------------------
#define ATT_BUF0   16384
#define ATT_BUFSZ  49152
#define SM_TOTAL   114688

__device__ __forceinline__ void load_kv(u32 sb, u32 bufbase, int b, int j0, int tid)
{
    const char* kh = (const char*)&g_kh[(size_t)(b * HW + j0) * DIM];
    const char* kl = (const char*)&g_kl[(size_t)(b * HW + j0) * DIM];
#pragma unroll
    for (int i = 0; i < 4; i++) {
        int id = tid + i * 256, row = id >> 3, g = id & 7;
        u32 o = swz128(row, g);
        u32 so = row * 128 + g * 16;
        CP16(sb + bufbase + o, kh + so);
        CP16(sb + bufbase + 16384 + o, kl + so);
    }
    const char* vh = (const char*)&g_vth[(size_t)b * DIM * HW + j0];
#pragma unroll
    for (int i = 0; i < 4; i++) {
        int id = tid + i * 256, d = id >> 4, g = id & 15;
        u32 o = swz256(d, g);
        u32 so = d * (HW * 2) + g * 16;
        CP16(sb + bufbase + 32768 + o, vh + so);
    }
}

__global__ __launch_bounds__(256, 2) void attn_kernel()
{
    extern __shared__ char sm[];
    const u32 sb = smem_u32(sm);
    const int tid  = threadIdx.x;
    const int lane = tid & 31;
    const int wid  = tid >> 5;   // 0..7
    const int wm = wid & 3;      // M group: rows wm*16 .. +15
    const int wn = wid >> 2;     // j half:  cols wn*64 .. +63
    const int b  = blockIdx.y;
    const int i0 = blockIdx.x * 64;
    const int g  = lane >> 2;
    const int t  = lane & 3;

    {
        const char* qh = (const char*)&g_qh[(size_t)(b * HW + i0) * DIM];
        const char* ql = (const char*)&g_ql[(size_t)(b * HW + i0) * DIM];
#pragma unroll
        for (int i = 0; i < 2; i++) {
            int id = tid + i * 256, row = id >> 3, gg = id & 7;
            u32 o = swz128(row, gg);
            u32 so = row * 128 + gg * 16;
            CP16(sb + 0 + o, qh + so);
            CP16(sb + 8192 + o, ql + so);
        }
        load_kv(sb, ATT_BUF0, b, 0, tid);
        CPC(); CPW0();
        __syncthreads();
    }

    // ---- Load Q fragments once; resident for the whole sweep ----
    u32 qfh[4][4], qfl[4][4];
    {
        const u32 q_row  = wm * 16 + (lane & 15);
        const u32 q_gsel = (u32)(lane >> 4);
#pragma unroll
        for (int kt = 0; kt < 4; kt++) {
            u32 off = swz128(q_row, q_gsel + kt * 2);
            ldsm4(qfh[kt], sb + 0 + off);
            ldsm4(qfl[kt], sb + 8192 + off);
        }
    }

    float oc[8][4];
    float lsum[2];
    lsum[0] = 0.0f; lsum[1] = 0.0f;
#pragma unroll
    for (int dnt = 0; dnt < 8; dnt++)
#pragma unroll
        for (int e = 0; e < 4; e++) oc[dnt][e] = 0.0f;

    const u32 b_ro = (u32)(((lane >> 4) << 3) + (lane & 7));
    const u32 b_gg = (u32)((lane >> 3) & 1);

    for (int jt = 0; jt < HW / 128; jt++) {
        CPW0();
        __syncthreads();
        const u32 buf = ATT_BUF0 + (u32)(jt & 1) * ATT_BUFSZ;
        if (jt + 1 < HW / 128)
            load_kv(sb, ATT_BUF0 + (u32)((jt + 1) & 1) * ATT_BUFSZ, b, (jt + 1) * 128, tid);
        CPC();

#pragma unroll
        for (int half = 0; half < 2; half++) {
            // ---- S for 32 j-cols (accumulator-alternating MMA order) ----
            float sc[4][4];
#pragma unroll
            for (int nt = 0; nt < 4; nt++)
#pragma unroll
                for (int e = 0; e < 4; e++) sc[nt][e] = 0.0f;

#pragma unroll
            for (int kt = 0; kt < 4; kt++) {
#pragma unroll
                for (int ntp = 0; ntp < 2; ntp++) {
                    u32 bh[4], bl[4];
                    u32 ro = (u32)(wn * 64 + half * 32 + ntp * 16) + b_ro;
                    u32 gg = b_gg + kt * 2;
                    u32 off = swz128(ro, gg);
                    ldsm4(bh, sb + buf + off);
                    ldsm4(bl, sb + buf + 16384 + off);
                    mma16816(sc[ntp * 2 + 0], qfh[kt], bh + 0);
                    mma16816(sc[ntp * 2 + 1], qfh[kt], bh + 2);
                    mma16816(sc[ntp * 2 + 0], qfh[kt], bl + 0);
                    mma16816(sc[ntp * 2 + 1], qfh[kt], bl + 2);
                    mma16816(sc[ntp * 2 + 0], qfl[kt], bh + 0);
                    mma16816(sc[ntp * 2 + 1], qfl[kt], bh + 2);
                }
            }

            // ---- softmax (ex2) + single-product PV, two 16-wide chunks ----
#pragma unroll
            for (int jj = 0; jj < 2; jj++) {
                const int jkt = half * 2 + jj;
                u32 ph[4];
#pragma unroll
                for (int h = 0; h < 2; h++) {
                    int nt = jj * 2 + h;
                    float e0 = ex2f(sc[nt][0]);
                    float e1 = ex2f(sc[nt][1]);
                    float e2 = ex2f(sc[nt][2]);
                    float e3 = ex2f(sc[nt][3]);
                    lsum[0] += e0 + e1;
                    lsum[1] += e2 + e3;
                    ph[h * 2 + 0] = packbf(e0, e1);
                    ph[h * 2 + 1] = packbf(e2, e3);
                }
#pragma unroll
                for (int dntp = 0; dntp < 4; dntp++) {
                    u32 bvh[4];
                    u32 ro = (u32)(dntp * 16) + b_ro;
                    u32 gg = (u32)(wn * 8 + jkt * 2) + b_gg;
                    u32 off = swz256(ro, gg);
                    ldsm4(bvh, sb + buf + 32768 + off);
                    mma16816(oc[dntp * 2 + 0], ph, bvh + 0);
                    mma16816(oc[dntp * 2 + 1], ph, bvh + 2);
                }
            }
        }
    }
    __syncthreads();   // protect smem-reuse writes below against last-tile reads

    // ---- epilogue: combine j-half partials, normalize, store hi/lo bf16 ----
    // reuse smem: op[wn] @ wn*16K (64 rows x 64 d fp32), lsum @ 32K
    float* lp = (float*)(sm + 32768);   // [wn][64]
#pragma unroll
    for (int r = 0; r < 2; r++) {
        float v = lsum[r];
        v += __shfl_xor_sync(0xffffffffu, v, 1);
        v += __shfl_xor_sync(0xffffffffu, v, 2);
        if (t == 0) lp[wn * 64 + wm * 16 + r * 8 + g] = v;
    }
    float* op = (float*)(sm + wn * 16384);
#pragma unroll
    for (int dnt = 0; dnt < 8; dnt++) {
        int r0 = wm * 16 + g;
        int c = dnt * 8 + t * 2;
        *(float2*)&op[r0 * 64 + c]       = make_float2(oc[dnt][0], oc[dnt][1]);
        *(float2*)&op[(r0 + 8) * 64 + c] = make_float2(oc[dnt][2], oc[dnt][3]);
    }
    __syncthreads();

    float* o0 = (float*)sm;
    float* o1 = (float*)(sm + 16384);
    float* lpf = (float*)(sm + 32768);
#pragma unroll
    for (int i = 0; i < 4; i++) {
        int idx = tid + i * 256;       // 0..1023
        int row = idx >> 4, c4 = (idx & 15) * 4;
        float invl = 1.0f / (lpf[row] + lpf[64 + row]);
        float4 a = *(float4*)&o0[row * 64 + c4];
        float4 bb = *(float4*)&o1[row * 64 + c4];
        float v0 = (a.x + bb.x) * invl;
        float v1 = (a.y + bb.y) * invl;
        float v2 = (a.z + bb.z) * invl;
        float v3 = (a.w + bb.w) * invl;
        u32 h01 = packbf(v0, v1); float2 f0 = unpackbf(h01);
        u32 l01 = packbf(v0 - f0.x, v1 - f0.y);
        u32 h23 = packbf(v2, v3); float2 f1 = unpackbf(h23);
        u32 l23 = packbf(v2 - f1.x, v3 - f1.y);
        size_t off = (size_t)(b * HW + i0 + row) * DIM + c4;
        *(uint2*)&g_sah[off] = make_uint2(h01, h23);
        *(uint2*)&g_sal[off] = make_uint2(l01, l23);
    }
}

// ---------------------------------------------------------------------------
// Kernel 3: output projection via HMMA hi/lo + bias + gamma + residual.
// ---------------------------------------------------------------------------
#define PROJ_SMEM 65536

__global__ __launch_bounds__(256, 2) void proj_mma_kernel(
    const float* __restrict__ x,
    const float* __restrict__ bsa,
    const float* __restrict__ gamma,
    float* __restrict__ out)
{
    extern __shared__ char sm[];
    const u32 sb = smem_u32(sm);
    const int tid  = threadIdx.x;
    const int lane = tid & 31;
    const int wid  = tid >> 5;
    const int wm = wid & 3;
    const int wn = wid >> 2;
    const int g  = lane >> 2;
    const int t  = lane & 3;
    const int b  = blockIdx.z;
    const int c0 = blockIdx.y * 128;
    const int n0 = blockIdx.x * 128;

    {
        const char* ah = (const char*)&g_wsah[(size_t)c0 * DIM];
        const char* al = (const char*)&g_wsal[(size_t)c0 * DIM];
        const char* bh = (const char*)&g_sah[(size_t)(b * HW + n0) * DIM];
        const char* bl = (const char*)&g_sal[(size_t)(b * HW + n0) * DIM];
#pragma unroll
        for (int i = 0; i < 4; i++) {
            int id = tid + i * 256;
            u32 row = (u32)(id >> 3), gg = (u32)(id & 7);
            u32 o = swz128(row, gg);
            u32 so = row * 128 + gg * 16;
            CP16(sb + o, ah + so);
            CP16(sb + 16384 + o, al + so);
            CP16(sb + 32768 + o, bh + so);
            CP16(sb + 49152 + o, bl + so);
        }
        CPC(); CPW0();
        __syncthreads();
    }

    float c[2][8][4];
#pragma unroll
    for (int mt = 0; mt < 2; mt++)
#pragma unroll
        for (int nt = 0; nt < 8; nt++)
#pragma unroll
            for (int e = 0; e < 4; e++) c[mt][nt][e] = 0.0f;

    const u32 a_row = wm * 32 + (lane & 15);
    const u32 a_g = (u32)(lane >> 4);
    const u32 b_row = wn * 64 + (lane & 7);
    const u32 b_g = (u32)((lane >> 3) & 1);

#pragma unroll
    for (int kt = 0; kt < 4; kt++) {
        u32 ah2[2][4], al2[2][4];
#pragma unroll
        for (int mt = 0; mt < 2; mt++) {
            u32 off = swz128(a_row + mt * 16, a_g + kt * 2);
            ldsm4(ah2[mt], sb + off);
            ldsm4(al2[mt], sb + 16384 + off);
        }
#pragma unroll
        for (int nt = 0; nt < 8; nt++) {
            u32 bh2[2], bl2[2];
            u32 off = swz128(b_row + nt * 8, b_g + kt * 2);
            ldsm2(bh2, sb + 32768 + off);
            ldsm2(bl2, sb + 49152 + off);
#pragma unroll
            for (int mt = 0; mt < 2; mt++) {
                mma16816(c[mt][nt], ah2[mt], bh2);
                mma16816(c[mt][nt], ah2[mt], bl2);
                mma16816(c[mt][nt], al2[mt], bh2);
            }
        }
    }

    const float gm = gamma[0];
#pragma unroll
    for (int mt = 0; mt < 2; mt++)
#pragma unroll
        for (int nt = 0; nt < 8; nt++) {
            int cg = c0 + wm * 32 + mt * 16 + g;
            int n  = n0 + wn * 64 + nt * 8 + t * 2;
            float b0 = bsa[cg], b1 = bsa[cg + 8];
            size_t off0 = ((size_t)(b * CIN) + cg) * HW + n;
            size_t off1 = off0 + (size_t)8 * HW;
            float2 xv0 = *(const float2*)&x[off0];
            float2 xv1 = *(const float2*)&x[off1];
            float2 o0, o1;
            o0.x = gm * (c[mt][nt][0] + b0) + xv0.x;
            o0.y = gm * (c[mt][nt][1] + b0) + xv0.y;
            o1.x = gm * (c[mt][nt][2] + b1) + xv1.x;
            o1.y = gm * (c[mt][nt][3] + b1) + xv1.y;
            *(float2*)&out[off0] = o0;
            *(float2*)&out[off1] = o1;
        }
}

// ---------------------------------------------------------------------------
extern "C" void kernel_launch(void* const* d_in, const int* in_sizes, int n_in,
                              void* d_out, int out_size)
{
    const float* x     = (const float*)d_in[0];
    const float* wq    = (const float*)d_in[1];
    const float* bq    = (const float*)d_in[2];
    const float* wk    = (const float*)d_in[3];
    const float* bk    = (const float*)d_in[4];
    const float* wv    = (const float*)d_in[5];
    const float* bv    = (const float*)d_in[6];
    const float* wsa   = (const float*)d_in[7];
    const float* bsa   = (const float*)d_in[8];
    const float* gamma = (const float*)d_in[9];
    float* out = (float*)d_out;

    cudaFuncSetAttribute(attn_kernel, cudaFuncAttributeMaxDynamicSharedMemorySize, SM_TOTAL);
    cudaFuncSetAttribute(qkv_mma_kernel, cudaFuncAttributeMaxDynamicSharedMemorySize, QKV_SMEM);
    cudaFuncSetAttribute(proj_mma_kernel, cudaFuncAttributeMaxDynamicSharedMemorySize, PROJ_SMEM);

    convert_x_kernel<<<dim3(HW / 64, CIN / 64, BATCH), 256>>>(x);
    convert_w_kernel<<<4, 256>>>(wq, wk, wv, wsa);
    qkv_mma_kernel<<<dim3(HW / 128, BATCH, 3), 256, QKV_SMEM>>>(bq, bk, bv);
    attn_kernel<<<dim3(HW / 64, BATCH), 256, SM_TOTAL>>>();
    proj_mma_kernel<<<dim3(HW / 128, CIN / 128, BATCH), 256, PROJ_SMEM>>>(x, bsa, gamma, out);
}

// round 13
// speedup vs baseline: 1.6373x; 1.6373x over previous
#include <cuda_runtime.h>
#include <cuda_bf16.h>
#include <cuda_fp16.h>
#include <math.h>
#include <stdint.h>
#include <string.h>

#define BATCH 4
#define CIN   256
#define HW    4096
#define DIM   64
#define LOG2E 1.4426950408889634f

typedef unsigned int u32;
typedef unsigned long long u64;

// ---------------------------------------------------------------------------
// Device scratch (fp16 single precision for GEMM operands; V/P stay bf16)
// ---------------------------------------------------------------------------
__device__ __half g_xt[BATCH * HW * CIN];          // x transposed [b][n][c]
__device__ __half g_w[3 * DIM * CIN];              // wq|wk|wv
__device__ __half g_wsa[CIN * DIM];
__device__ __half g_q[BATCH * HW * DIM];           // pre-scaled by log2(e)
__device__ __half g_k[BATCH * HW * DIM];
__device__ __nv_bfloat16 g_vth[BATCH * DIM * HW];  // [b][d][j] bf16
__device__ __half g_sa[BATCH * HW * DIM];          // attention out [b][n][d]

// ---------------------------------------------------------------------------
// Helpers
// ---------------------------------------------------------------------------
__device__ __forceinline__ uint32_t smem_u32(const void* p) {
    uint32_t a;
    asm("{ .reg .u64 t; cvta.to.shared.u64 t, %1; cvt.u32.u64 %0, t; }" : "=r"(a) : "l"(p));
    return a;
}
// pack two floats into bf16x2: lo -> bits[15:0], hi -> bits[31:16]
__device__ __forceinline__ u32 packbf(float lo, float hi) {
    u32 r;
    asm("cvt.rn.bf16x2.f32 %0, %1, %2;" : "=r"(r) : "f"(hi), "f"(lo));
    return r;
}
// pack two floats into f16x2
__device__ __forceinline__ u32 packhf(float lo, float hi) {
    u32 r;
    asm("cvt.rn.f16x2.f32 %0, %1, %2;" : "=r"(r) : "f"(hi), "f"(lo));
    return r;
}
__device__ __forceinline__ float ex2f(float x) {
    float r;
    asm("ex2.approx.f32 %0, %1;" : "=f"(r) : "f"(x));
    return r;
}
// bf16 mma
__device__ __forceinline__ void mma16816(float* c, const u32* a, const u32* b) {
    asm volatile(
        "mma.sync.aligned.m16n8k16.row.col.f32.bf16.bf16.f32 "
        "{%0,%1,%2,%3}, {%4,%5,%6,%7}, {%8,%9}, {%0,%1,%2,%3};"
        : "+f"(c[0]), "+f"(c[1]), "+f"(c[2]), "+f"(c[3])
        : "r"(a[0]), "r"(a[1]), "r"(a[2]), "r"(a[3]), "r"(b[0]), "r"(b[1]));
}
// fp16 mma
__device__ __forceinline__ void mma16816h(float* c, const u32* a, const u32* b) {
    asm volatile(
        "mma.sync.aligned.m16n8k16.row.col.f32.f16.f16.f32 "
        "{%0,%1,%2,%3}, {%4,%5,%6,%7}, {%8,%9}, {%0,%1,%2,%3};"
        : "+f"(c[0]), "+f"(c[1]), "+f"(c[2]), "+f"(c[3])
        : "r"(a[0]), "r"(a[1]), "r"(a[2]), "r"(a[3]), "r"(b[0]), "r"(b[1]));
}
__device__ __forceinline__ void ldsm4(u32* r, uint32_t addr) {
    asm volatile("ldmatrix.sync.aligned.m8n8.x4.shared.b16 {%0,%1,%2,%3}, [%4];"
        : "=r"(r[0]), "=r"(r[1]), "=r"(r[2]), "=r"(r[3]) : "r"(addr));
}
__device__ __forceinline__ void ldsm2(u32* r, uint32_t addr) {
    asm volatile("ldmatrix.sync.aligned.m8n8.x2.shared.b16 {%0,%1}, [%2];"
        : "=r"(r[0]), "=r"(r[1]) : "r"(addr));
}
#define CP16(dst, src) asm volatile("cp.async.cg.shared.global [%0], [%1], 16;" :: "r"(dst), "l"(src))
#define CPC()  asm volatile("cp.async.commit_group;")
#define CPW0() asm volatile("cp.async.wait_group 0;")

// XOR swizzles for 128B / 256B / 512B rows (16B granules)
__device__ __forceinline__ u32 swz128(u32 row, u32 g) { return row * 128u + ((g ^ (row & 7u)) << 4); }
__device__ __forceinline__ u32 swz256(u32 row, u32 g) { return row * 256u + (((g & 8u) | ((g & 7u) ^ (row & 7u))) << 4); }
__device__ __forceinline__ u32 swz512(u32 row, u32 g) { return row * 512u + (((g & 24u) | ((g & 7u) ^ (row & 7u))) << 4); }

// ---------------------------------------------------------------------------
// Kernel 0a: x [b][c][n] fp32 -> xt fp16 [b][n][c] (tile transpose)
// ---------------------------------------------------------------------------
__global__ __launch_bounds__(256) void convert_x_kernel(const float* __restrict__ x)
{
    __shared__ float xs[64][65];
    const int b  = blockIdx.z;
    const int c0 = blockIdx.y * 64;
    const int n0 = blockIdx.x * 64;
    const int tid = threadIdx.x;

#pragma unroll
    for (int i = 0; i < 4; i++) {
        int r = (tid >> 4) + i * 16;
        int col4 = (tid & 15) * 4;
        float4 v = *(const float4*)&x[(size_t)(b * CIN + c0 + r) * HW + n0 + col4];
        xs[r][col4 + 0] = v.x;
        xs[r][col4 + 1] = v.y;
        xs[r][col4 + 2] = v.z;
        xs[r][col4 + 3] = v.w;
    }
    __syncthreads();

    const int n  = tid >> 2;
    const int cs = (tid & 3) * 16;
    u32 hh[8];
#pragma unroll
    for (int j = 0; j < 16; j += 2)
        hh[j >> 1] = packhf(xs[cs + j][n], xs[cs + j + 1][n]);
    size_t base = ((size_t)(b * HW) + n0 + n) * CIN + c0 + cs;
    *(uint4*)&g_xt[base]     = *(uint4*)&hh[0];
    *(uint4*)&g_xt[base + 8] = *(uint4*)&hh[4];
}

// ---------------------------------------------------------------------------
// Kernel 0b: weight conversion -> fp16
// ---------------------------------------------------------------------------
__global__ void convert_w_kernel(const float* __restrict__ wq, const float* __restrict__ wk,
                                 const float* __restrict__ wv, const float* __restrict__ wsa)
{
    const int p = blockIdx.x;
    const float* s = (p == 0) ? wq : (p == 1) ? wk : (p == 2) ? wv : wsa;
    __half* d = (p < 3) ? &g_w[p * DIM * CIN] : g_wsa;
    for (int i = threadIdx.x; i < DIM * CIN; i += blockDim.x)
        d[i] = __float2half(s[i]);
}

// ---------------------------------------------------------------------------
// Kernel 1: QKV projections via single fp16 HMMA.
// out[n][d] = xt[n][c] . w[d][c]^T + bias.  M=128 (n), N=64 (d), K=256.
// q output pre-scaled by log2(e).
// Smem: A @0 (64K), B @64K (32K) = 96K.
// ---------------------------------------------------------------------------
#define QKV_SMEM 98304

__global__ __launch_bounds__(256, 1) void qkv_mma_kernel(
    const float* __restrict__ bq, const float* __restrict__ bk, const float* __restrict__ bv)
{
    extern __shared__ char sm[];
    const u32 sb = smem_u32(sm);
    const int tid  = threadIdx.x;
    const int lane = tid & 31;
    const int wid  = tid >> 5;
    const int wm = wid & 3;
    const int wn = wid >> 2;
    const int g  = lane >> 2;
    const int t  = lane & 3;
    const int b  = blockIdx.y;
    const int p  = blockIdx.z;
    const int i0 = blockIdx.x * 128;
    const float* bias = (p == 0) ? bq : (p == 1) ? bk : bv;
    const float scl = (p == 0) ? LOG2E : 1.0f;

    {
        const char* ah = (const char*)&g_xt[(size_t)(b * HW + i0) * CIN];
#pragma unroll
        for (int i = 0; i < 16; i++) {
            int id = tid + i * 256;
            u32 row = (u32)(id >> 5), gg = (u32)(id & 31);
            CP16(sb + swz512(row, gg), ah + row * 512 + gg * 16);
        }
        const char* bh = (const char*)&g_w[p * DIM * CIN];
#pragma unroll
        for (int i = 0; i < 8; i++) {
            int id = tid + i * 256;
            u32 row = (u32)(id >> 5), gg = (u32)(id & 31);
            CP16(sb + 65536 + swz512(row, gg), bh + row * 512 + gg * 16);
        }
        CPC(); CPW0();
        __syncthreads();
    }

    float c[2][4][4];
#pragma unroll
    for (int mt = 0; mt < 2; mt++)
#pragma unroll
        for (int nt = 0; nt < 4; nt++)
#pragma unroll
            for (int e = 0; e < 4; e++) c[mt][nt][e] = 0.0f;

    const u32 a_row = wm * 32 + (lane & 15);
    const u32 a_g = (u32)(lane >> 4);
    const u32 b_row = wn * 32 + (lane & 7);
    const u32 b_g = (u32)((lane >> 3) & 1);

#pragma unroll
    for (int kt = 0; kt < 16; kt++) {
        u32 ah2[2][4];
#pragma unroll
        for (int mt = 0; mt < 2; mt++)
            ldsm4(ah2[mt], sb + swz512(a_row + mt * 16, a_g + kt * 2));
#pragma unroll
        for (int nt = 0; nt < 4; nt++) {
            u32 bh2[2];
            ldsm2(bh2, sb + 65536 + swz512(b_row + nt * 8, b_g + kt * 2));
#pragma unroll
            for (int mt = 0; mt < 2; mt++)
                mma16816h(c[mt][nt], ah2[mt], bh2);
        }
    }

    if (p < 2) {
        __half* oh = (p == 0) ? g_q : g_k;
#pragma unroll
        for (int mt = 0; mt < 2; mt++)
#pragma unroll
            for (int nt = 0; nt < 4; nt++) {
                int n = i0 + wm * 32 + mt * 16 + g;
                int d = wn * 32 + nt * 8 + t * 2;
                float b0 = bias[d], b1 = bias[d + 1];
                float v0 = (c[mt][nt][0] + b0) * scl, v1 = (c[mt][nt][1] + b1) * scl;
                float v2 = (c[mt][nt][2] + b0) * scl, v3 = (c[mt][nt][3] + b1) * scl;
                size_t o0 = (size_t)(b * HW + n) * DIM + d;
                size_t o1 = (size_t)(b * HW + n + 8) * DIM + d;
                *(u32*)&oh[o0] = packhf(v0, v1);
                *(u32*)&oh[o1] = packhf(v2, v3);
            }
    } else {
        // v: bounce through smem, store bf16 [d][n]
        float* ot = (float*)sm;   // [64 d][128 n] = 32KB
        __syncthreads();
#pragma unroll
        for (int mt = 0; mt < 2; mt++)
#pragma unroll
            for (int nt = 0; nt < 4; nt++) {
                int n = wm * 32 + mt * 16 + g;
                int d = wn * 32 + nt * 8 + t * 2;
                ot[d * 128 + n]           = c[mt][nt][0];
                ot[(d + 1) * 128 + n]     = c[mt][nt][1];
                ot[d * 128 + n + 8]       = c[mt][nt][2];
                ot[(d + 1) * 128 + n + 8] = c[mt][nt][3];
            }
        __syncthreads();
        int d  = tid >> 2;
        int ns = (tid & 3) * 32;
        float bvv = bias[d];
        u32 hh[16];
#pragma unroll
        for (int j = 0; j < 32; j += 2) {
            float v0 = ot[d * 128 + ns + j] + bvv;
            float v1 = ot[d * 128 + ns + j + 1] + bvv;
            hh[j >> 1] = packbf(v0, v1);
        }
        size_t base = (size_t)(b * DIM + d) * HW + i0 + ns;
#pragma unroll
        for (int q4 = 0; q4 < 4; q4++)
            *(uint4*)&g_vth[base + q4 * 8] = *(uint4*)&hh[q4 * 4];
    }
}

// ---------------------------------------------------------------------------
// Kernel 2: HMMA flash attention. 512 threads = 16 warps (8 M-groups of 16
// rows x 2 j-halves of 64). Q fp16 register-resident; S single fp16 product;
// PV single bf16 product (p unnormalized needs fp32-range -> bf16).
// Smem: Q @0 (16K) | buf0 16K..48K (K 16K + V 16K) | buf1 48K..80K
// ---------------------------------------------------------------------------
#define ATT_BUF0   16384
#define ATT_BUFSZ  32768
#define SM_TOTAL   81920

__device__ __forceinline__ void load_kv(u32 sb, u32 bufbase, int b, int j0, int tid)
{
    const char* kh = (const char*)&g_k[(size_t)(b * HW + j0) * DIM];
#pragma unroll
    for (int i = 0; i < 2; i++) {
        int id = tid + i * 512, row = id >> 3, g = id & 7;
        CP16(sb + bufbase + swz128(row, g), kh + row * 128 + g * 16);
    }
    const char* vh = (const char*)&g_vth[(size_t)b * DIM * HW + j0];
#pragma unroll
    for (int i = 0; i < 2; i++) {
        int id = tid + i * 512, d = id >> 4, g = id & 15;
        CP16(sb + bufbase + 16384 + swz256(d, g), vh + d * (HW * 2) + g * 16);
    }
}

__global__ __launch_bounds__(512, 1) void attn_kernel()
{
    extern __shared__ char sm[];
    const u32 sb = smem_u32(sm);
    const int tid  = threadIdx.x;
    const int lane = tid & 31;
    const int wid  = tid >> 5;   // 0..15
    const int wm = wid & 7;      // M group: rows wm*16 .. +15
    const int wn = wid >> 3;     // j half:  cols wn*64 .. +63
    const int b  = blockIdx.y;
    const int i0 = blockIdx.x * 128;
    const int g  = lane >> 2;
    const int t  = lane & 3;

    {
        const char* qh = (const char*)&g_q[(size_t)(b * HW + i0) * DIM];
#pragma unroll
        for (int i = 0; i < 2; i++) {
            int id = tid + i * 512, row = id >> 3, gg = id & 7;
            CP16(sb + swz128(row, gg), qh + row * 128 + gg * 16);
        }
        load_kv(sb, ATT_BUF0, b, 0, tid);
        CPC(); CPW0();
        __syncthreads();
    }

    // ---- Load Q fragments once; resident for the whole sweep ----
    u32 qf[4][4];
    {
        const u32 q_row  = wm * 16 + (lane & 15);
        const u32 q_gsel = (u32)(lane >> 4);
#pragma unroll
        for (int kt = 0; kt < 4; kt++)
            ldsm4(qf[kt], sb + swz128(q_row, q_gsel + kt * 2));
    }

    float oc[8][4];
    float lsum[2];
    lsum[0] = 0.0f; lsum[1] = 0.0f;
#pragma unroll
    for (int dnt = 0; dnt < 8; dnt++)
#pragma unroll
        for (int e = 0; e < 4; e++) oc[dnt][e] = 0.0f;

    const u32 b_ro = (u32)(((lane >> 4) << 3) + (lane & 7));
    const u32 b_gg = (u32)((lane >> 3) & 1);

    for (int jt = 0; jt < HW / 128; jt++) {
        CPW0();
        __syncthreads();
        const u32 buf = ATT_BUF0 + (u32)(jt & 1) * ATT_BUFSZ;
        if (jt + 1 < HW / 128)
            load_kv(sb, ATT_BUF0 + (u32)((jt + 1) & 1) * ATT_BUFSZ, b, (jt + 1) * 128, tid);
        CPC();

#pragma unroll
        for (int half = 0; half < 2; half++) {
            // ---- S for 32 j-cols: single fp16 product ----
            float sc[4][4];
#pragma unroll
            for (int nt = 0; nt < 4; nt++)
#pragma unroll
                for (int e = 0; e < 4; e++) sc[nt][e] = 0.0f;

#pragma unroll
            for (int kt = 0; kt < 4; kt++) {
#pragma unroll
                for (int ntp = 0; ntp < 2; ntp++) {
                    u32 bh[4];
                    u32 ro = (u32)(wn * 64 + half * 32 + ntp * 16) + b_ro;
                    ldsm4(bh, sb + buf + swz128(ro, b_gg + kt * 2));
                    mma16816h(sc[ntp * 2 + 0], qf[kt], bh + 0);
                    mma16816h(sc[ntp * 2 + 1], qf[kt], bh + 2);
                }
            }

            // ---- softmax (ex2) + single-product bf16 PV ----
#pragma unroll
            for (int jj = 0; jj < 2; jj++) {
                const int jkt = half * 2 + jj;
                u32 ph[4];
#pragma unroll
                for (int h = 0; h < 2; h++) {
                    int nt = jj * 2 + h;
                    float e0 = ex2f(sc[nt][0]);
                    float e1 = ex2f(sc[nt][1]);
                    float e2 = ex2f(sc[nt][2]);
                    float e3 = ex2f(sc[nt][3]);
                    lsum[0] += e0 + e1;
                    lsum[1] += e2 + e3;
                    ph[h * 2 + 0] = packbf(e0, e1);
                    ph[h * 2 + 1] = packbf(e2, e3);
                }
#pragma unroll
                for (int dntp = 0; dntp < 4; dntp++) {
                    u32 bvh[4];
                    u32 ro = (u32)(dntp * 16) + b_ro;
                    u32 gg = (u32)(wn * 8 + jkt * 2) + b_gg;
                    ldsm4(bvh, sb + buf + 16384 + swz256(ro, gg));
                    mma16816(oc[dntp * 2 + 0], ph, bvh + 0);
                    mma16816(oc[dntp * 2 + 1], ph, bvh + 2);
                }
            }
        }
    }
    __syncthreads();   // protect smem-reuse writes below against last-tile reads

    // ---- epilogue: combine j-half partials, normalize, store fp16 ----
    float* lp = (float*)(sm + 65536);   // [wn][128]
#pragma unroll
    for (int r = 0; r < 2; r++) {
        float v = lsum[r];
        v += __shfl_xor_sync(0xffffffffu, v, 1);
        v += __shfl_xor_sync(0xffffffffu, v, 2);
        if (t == 0) lp[wn * 128 + wm * 16 + r * 8 + g] = v;
    }
    float* op = (float*)(sm + wn * 32768);
#pragma unroll
    for (int dnt = 0; dnt < 8; dnt++) {
        int r0 = wm * 16 + g;
        int c = dnt * 8 + t * 2;
        *(float2*)&op[r0 * 64 + c]       = make_float2(oc[dnt][0], oc[dnt][1]);
        *(float2*)&op[(r0 + 8) * 64 + c] = make_float2(oc[dnt][2], oc[dnt][3]);
    }
    __syncthreads();

    float* o0 = (float*)sm;
    float* o1 = (float*)(sm + 32768);
    float* lpf = (float*)(sm + 65536);
#pragma unroll
    for (int i = 0; i < 4; i++) {
        int idx = tid + i * 512;
        int row = idx >> 4, c4 = (idx & 15) * 4;
        float invl = 1.0f / (lpf[row] + lpf[128 + row]);
        float4 a = *(float4*)&o0[row * 64 + c4];
        float4 bb = *(float4*)&o1[row * 64 + c4];
        float v0 = (a.x + bb.x) * invl;
        float v1 = (a.y + bb.y) * invl;
        float v2 = (a.z + bb.z) * invl;
        float v3 = (a.w + bb.w) * invl;
        size_t off = (size_t)(b * HW + i0 + row) * DIM + c4;
        *(uint2*)&g_sa[off] = make_uint2(packhf(v0, v1), packhf(v2, v3));
    }
}

// ---------------------------------------------------------------------------
// Kernel 3: output projection via single fp16 HMMA + bias + gamma + residual.
// Smem: A @0 (16K), B @16K (16K) = 32K.
// ---------------------------------------------------------------------------
#define PROJ_SMEM 32768

__global__ __launch_bounds__(256, 2) void proj_mma_kernel(
    const float* __restrict__ x,
    const float* __restrict__ bsa,
    const float* __restrict__ gamma,
    float* __restrict__ out)
{
    extern __shared__ char sm[];
    const u32 sb = smem_u32(sm);
    const int tid  = threadIdx.x;
    const int lane = tid & 31;
    const int wid  = tid >> 5;
    const int wm = wid & 3;
    const int wn = wid >> 2;
    const int g  = lane >> 2;
    const int t  = lane & 3;
    const int b  = blockIdx.z;
    const int c0 = blockIdx.y * 128;
    const int n0 = blockIdx.x * 128;

    {
        const char* ah = (const char*)&g_wsa[(size_t)c0 * DIM];
        const char* bh = (const char*)&g_sa[(size_t)(b * HW + n0) * DIM];
#pragma unroll
        for (int i = 0; i < 4; i++) {
            int id = tid + i * 256;
            u32 row = (u32)(id >> 3), gg = (u32)(id & 7);
            u32 o = swz128(row, gg);
            u32 so = row * 128 + gg * 16;
            CP16(sb + o, ah + so);
            CP16(sb + 16384 + o, bh + so);
        }
        CPC(); CPW0();
        __syncthreads();
    }

    float c[2][8][4];
#pragma unroll
    for (int mt = 0; mt < 2; mt++)
#pragma unroll
        for (int nt = 0; nt < 8; nt++)
#pragma unroll
            for (int e = 0; e < 4; e++) c[mt][nt][e] = 0.0f;

    const u32 a_row = wm * 32 + (lane & 15);
    const u32 a_g = (u32)(lane >> 4);
    const u32 b_row = wn * 64 + (lane & 7);
    const u32 b_g = (u32)((lane >> 3) & 1);

#pragma unroll
    for (int kt = 0; kt < 4; kt++) {
        u32 ah2[2][4];
#pragma unroll
        for (int mt = 0; mt < 2; mt++)
            ldsm4(ah2[mt], sb + swz128(a_row + mt * 16, a_g + kt * 2));
#pragma unroll
        for (int nt = 0; nt < 8; nt++) {
            u32 bh2[2];
            ldsm2(bh2, sb + 16384 + swz128(b_row + nt * 8, b_g + kt * 2));
#pragma unroll
            for (int mt = 0; mt < 2; mt++)
                mma16816h(c[mt][nt], ah2[mt], bh2);
        }
    }

    const float gm = gamma[0];
#pragma unroll
    for (int mt = 0; mt < 2; mt++)
#pragma unroll
        for (int nt = 0; nt < 8; nt++) {
            int cg = c0 + wm * 32 + mt * 16 + g;
            int n  = n0 + wn * 64 + nt * 8 + t * 2;
            float b0 = bsa[cg], b1 = bsa[cg + 8];
            size_t off0 = ((size_t)(b * CIN) + cg) * HW + n;
            size_t off1 = off0 + (size_t)8 * HW;
            float2 xv0 = *(const float2*)&x[off0];
            float2 xv1 = *(const float2*)&x[off1];
            float2 o0, o1;
            o0.x = gm * (c[mt][nt][0] + b0) + xv0.x;
            o0.y = gm * (c[mt][nt][1] + b0) + xv0.y;
            o1.x = gm * (c[mt][nt][2] + b1) + xv1.x;
            o1.y = gm * (c[mt][nt][3] + b1) + xv1.y;
            *(float2*)&out[off0] = o0;
            *(float2*)&out[off1] = o1;
        }
}

// ---------------------------------------------------------------------------
extern "C" void kernel_launch(void* const* d_in, const int* in_sizes, int n_in,
                              void* d_out, int out_size)
{
    const float* x     = (const float*)d_in[0];
    const float* wq    = (const float*)d_in[1];
    const float* bq    = (const float*)d_in[2];
    const float* wk    = (const float*)d_in[3];
    const float* bk    = (const float*)d_in[4];
    const float* wv    = (const float*)d_in[5];
    const float* bv    = (const float*)d_in[6];
    const float* wsa   = (const float*)d_in[7];
    const float* bsa   = (const float*)d_in[8];
    const float* gamma = (const float*)d_in[9];
    float* out = (float*)d_out;

    cudaFuncSetAttribute(attn_kernel, cudaFuncAttributeMaxDynamicSharedMemorySize, SM_TOTAL);
    cudaFuncSetAttribute(qkv_mma_kernel, cudaFuncAttributeMaxDynamicSharedMemorySize, QKV_SMEM);
    cudaFuncSetAttribute(proj_mma_kernel, cudaFuncAttributeMaxDynamicSharedMemorySize, PROJ_SMEM);

    convert_x_kernel<<<dim3(HW / 64, CIN / 64, BATCH), 256>>>(x);
    convert_w_kernel<<<4, 256>>>(wq, wk, wv, wsa);
    qkv_mma_kernel<<<dim3(HW / 128, BATCH, 3), 256, QKV_SMEM>>>(bq, bk, bv);
    attn_kernel<<<dim3(HW / 128, BATCH), 512, SM_TOTAL>>>();
    proj_mma_kernel<<<dim3(HW / 128, CIN / 128, BATCH), 256, PROJ_SMEM>>>(x, bsa, gamma, out);
}

// round 14
// speedup vs baseline: 1.7322x; 1.0579x over previous
#include <cuda_runtime.h>
#include <cuda_bf16.h>
#include <cuda_fp16.h>
#include <math.h>
#include <stdint.h>
#include <string.h>

#define BATCH 4
#define CIN   256
#define HW    4096
#define DIM   64
#define LOG2E 1.4426950408889634f

typedef unsigned int u32;
typedef unsigned long long u64;

// ---------------------------------------------------------------------------
// Device scratch
// ---------------------------------------------------------------------------
__device__ __half g_w[3 * DIM * CIN];              // wq|wk|wv stacked [192][256]
__device__ __half g_wsa[CIN * DIM];
__device__ __half g_q[BATCH * HW * DIM];           // pre-scaled by log2(e)
__device__ __half g_k[BATCH * HW * DIM];
__device__ __nv_bfloat16 g_vth[BATCH * DIM * HW];  // [b][d][j] bf16
__device__ __half g_sa[BATCH * HW * DIM];          // attention out [b][n][d]

// ---------------------------------------------------------------------------
// Helpers
// ---------------------------------------------------------------------------
__device__ __forceinline__ uint32_t smem_u32(const void* p) {
    uint32_t a;
    asm("{ .reg .u64 t; cvta.to.shared.u64 t, %1; cvt.u32.u64 %0, t; }" : "=r"(a) : "l"(p));
    return a;
}
__device__ __forceinline__ u32 packbf(float lo, float hi) {
    u32 r;
    asm("cvt.rn.bf16x2.f32 %0, %1, %2;" : "=r"(r) : "f"(hi), "f"(lo));
    return r;
}
__device__ __forceinline__ u32 packhf(float lo, float hi) {
    u32 r;
    asm("cvt.rn.f16x2.f32 %0, %1, %2;" : "=r"(r) : "f"(hi), "f"(lo));
    return r;
}
__device__ __forceinline__ float ex2f(float x) {
    float r;
    asm("ex2.approx.f32 %0, %1;" : "=f"(r) : "f"(x));
    return r;
}
__device__ __forceinline__ void mma16816(float* c, const u32* a, const u32* b) {
    asm volatile(
        "mma.sync.aligned.m16n8k16.row.col.f32.bf16.bf16.f32 "
        "{%0,%1,%2,%3}, {%4,%5,%6,%7}, {%8,%9}, {%0,%1,%2,%3};"
        : "+f"(c[0]), "+f"(c[1]), "+f"(c[2]), "+f"(c[3])
        : "r"(a[0]), "r"(a[1]), "r"(a[2]), "r"(a[3]), "r"(b[0]), "r"(b[1]));
}
__device__ __forceinline__ void mma16816h(float* c, const u32* a, const u32* b) {
    asm volatile(
        "mma.sync.aligned.m16n8k16.row.col.f32.f16.f16.f32 "
        "{%0,%1,%2,%3}, {%4,%5,%6,%7}, {%8,%9}, {%0,%1,%2,%3};"
        : "+f"(c[0]), "+f"(c[1]), "+f"(c[2]), "+f"(c[3])
        : "r"(a[0]), "r"(a[1]), "r"(a[2]), "r"(a[3]), "r"(b[0]), "r"(b[1]));
}
__device__ __forceinline__ void ldsm4(u32* r, uint32_t addr) {
    asm volatile("ldmatrix.sync.aligned.m8n8.x4.shared.b16 {%0,%1,%2,%3}, [%4];"
        : "=r"(r[0]), "=r"(r[1]), "=r"(r[2]), "=r"(r[3]) : "r"(addr));
}
__device__ __forceinline__ void ldsm2(u32* r, uint32_t addr) {
    asm volatile("ldmatrix.sync.aligned.m8n8.x2.shared.b16 {%0,%1}, [%2];"
        : "=r"(r[0]), "=r"(r[1]) : "r"(addr));
}
#define CP16(dst, src) asm volatile("cp.async.cg.shared.global [%0], [%1], 16;" :: "r"(dst), "l"(src))
#define CPC()  asm volatile("cp.async.commit_group;")
#define CPW0() asm volatile("cp.async.wait_group 0;")

__device__ __forceinline__ u32 swz128(u32 row, u32 g) { return row * 128u + ((g ^ (row & 7u)) << 4); }
__device__ __forceinline__ u32 swz256(u32 row, u32 g) { return row * 256u + (((g & 8u) | ((g & 7u) ^ (row & 7u))) << 4); }
__device__ __forceinline__ u32 swz512(u32 row, u32 g) { return row * 512u + (((g & 24u) | ((g & 7u) ^ (row & 7u))) << 4); }

// ---------------------------------------------------------------------------
// Kernel 0: weight conversion -> fp16
// ---------------------------------------------------------------------------
__global__ void convert_w_kernel(const float* __restrict__ wq, const float* __restrict__ wk,
                                 const float* __restrict__ wv, const float* __restrict__ wsa)
{
    const int p = blockIdx.x;
    const float* s = (p == 0) ? wq : (p == 1) ? wk : (p == 2) ? wv : wsa;
    __half* d = (p < 3) ? &g_w[p * DIM * CIN] : g_wsa;
    for (int i = threadIdx.x; i < DIM * CIN; i += blockDim.x)
        d[i] = __float2half(s[i]);
}

// ---------------------------------------------------------------------------
// Kernel 1: FUSED x-transpose + QKV projections (fp16 HMMA).
// Per CTA: transpose x[256c][128n] fp32 -> A[128n][256c] fp16 in smem,
// then 3 projections (wq,wk,wv all resident in B smem).
// Smem: A @0 (64K) | B @64K (96K, 192 rows) | XS @160K (fp32 staging, 33.8K)
// ---------------------------------------------------------------------------
#define QF_A   0
#define QF_B   65536
#define QF_XS  163840
#define QF_SMEM 197632
#define XS_STRIDE 132   // fp32 elements per staged row (128 + 4 pad)

__global__ __launch_bounds__(256, 1) void qkv_fused_kernel(
    const float* __restrict__ x,
    const float* __restrict__ bq, const float* __restrict__ bk, const float* __restrict__ bv)
{
    extern __shared__ char sm[];
    const u32 sb = smem_u32(sm);
    const int tid  = threadIdx.x;
    const int lane = tid & 31;
    const int wid  = tid >> 5;
    const int wm = wid & 3;
    const int wn = wid >> 2;
    const int g  = lane >> 2;
    const int t  = lane & 3;
    const int b  = blockIdx.y;
    const int i0 = blockIdx.x * 128;

    // ---- load all 3 weight matrices into B ----
#pragma unroll
    for (int i = 0; i < 24; i++) {
        int id = tid + i * 256;
        u32 row = (u32)(id >> 5), gg = (u32)(id & 31);
        CP16(sb + QF_B + swz512(row, gg), (const char*)g_w + row * 512 + gg * 16);
    }
    CPC();

    // ---- transpose x -> A, 4 chunks of 64 c ----
    float* xs = (float*)(sm + QF_XS);
    const int tn  = (lane) + ((tid >> 5) & 3) * 32;   // n: 0..127
    const int glh = (tid >> 7) * 4;                   // granule-local base 0 or 4
    for (int kc = 0; kc < 4; kc++) {
        CPW0();               // drain B on first iter / previous xs
        __syncthreads();      // xs free for rewrite
#pragma unroll
        for (int i = 0; i < 8; i++) {
            int id = tid + i * 256;
            int r = id >> 5, gg = id & 31;
            CP16(sb + QF_XS + r * (XS_STRIDE * 4) + gg * 16,
                 (const char*)&x[(size_t)(b * CIN + kc * 64 + r) * HW + i0] + gg * 16);
        }
        CPC(); CPW0();
        __syncthreads();
#pragma unroll
        for (int gi = 0; gi < 4; gi++) {
            int gl = glh + gi;          // 0..7
            u32 w4[4];
#pragma unroll
            for (int s = 0; s < 4; s++) {
                float f0 = xs[(gl * 8 + 2 * s)     * XS_STRIDE + tn];
                float f1 = xs[(gl * 8 + 2 * s + 1) * XS_STRIDE + tn];
                w4[s] = packhf(f0, f1);
            }
            u32 gran = (u32)(kc * 8 + gl);
            *(uint4*)(sm + QF_A + swz512((u32)tn, gran)) = *(uint4*)w4;
        }
    }
    __syncthreads();

    const u32 a_row = wm * 32 + (lane & 15);
    const u32 a_g = (u32)(lane >> 4);
    const u32 b_rl = (u32)(lane & 7);
    const u32 b_g = (u32)((lane >> 3) & 1);

    for (int p = 0; p < 3; p++) {
        const float* bias = (p == 0) ? bq : (p == 1) ? bk : bv;
        const float scl = (p == 0) ? LOG2E : 1.0f;

        float c[2][4][4];
#pragma unroll
        for (int mt = 0; mt < 2; mt++)
#pragma unroll
            for (int nt = 0; nt < 4; nt++)
#pragma unroll
                for (int e = 0; e < 4; e++) c[mt][nt][e] = 0.0f;

#pragma unroll
        for (int kt = 0; kt < 16; kt++) {
            u32 ah2[2][4];
#pragma unroll
            for (int mt = 0; mt < 2; mt++)
                ldsm4(ah2[mt], sb + QF_A + swz512(a_row + mt * 16, a_g + kt * 2));
#pragma unroll
            for (int nt = 0; nt < 4; nt++) {
                u32 bh2[2];
                u32 row = (u32)(p * 64 + wn * 32 + nt * 8) + b_rl;
                ldsm2(bh2, sb + QF_B + swz512(row, b_g + kt * 2));
#pragma unroll
                for (int mt = 0; mt < 2; mt++)
                    mma16816h(c[mt][nt], ah2[mt], bh2);
            }
        }

        if (p < 2) {
            __half* oh = (p == 0) ? g_q : g_k;
#pragma unroll
            for (int mt = 0; mt < 2; mt++)
#pragma unroll
                for (int nt = 0; nt < 4; nt++) {
                    int n = i0 + wm * 32 + mt * 16 + g;
                    int d = wn * 32 + nt * 8 + t * 2;
                    float b0 = bias[d], b1 = bias[d + 1];
                    float v0 = (c[mt][nt][0] + b0) * scl, v1 = (c[mt][nt][1] + b1) * scl;
                    float v2 = (c[mt][nt][2] + b0) * scl, v3 = (c[mt][nt][3] + b1) * scl;
                    size_t o0 = (size_t)(b * HW + n) * DIM + d;
                    size_t o1 = (size_t)(b * HW + n + 8) * DIM + d;
                    *(u32*)&oh[o0] = packhf(v0, v1);
                    *(u32*)&oh[o1] = packhf(v2, v3);
                }
        } else {
            // v: transpose through XS region, store bf16 [d][n]
            float* ot = (float*)(sm + QF_XS);   // [64 d][128 n] fp32 = 32KB
            __syncthreads();
#pragma unroll
            for (int mt = 0; mt < 2; mt++)
#pragma unroll
                for (int nt = 0; nt < 4; nt++) {
                    int n = wm * 32 + mt * 16 + g;
                    int d = wn * 32 + nt * 8 + t * 2;
                    ot[d * 128 + n]           = c[mt][nt][0];
                    ot[(d + 1) * 128 + n]     = c[mt][nt][1];
                    ot[d * 128 + n + 8]       = c[mt][nt][2];
                    ot[(d + 1) * 128 + n + 8] = c[mt][nt][3];
                }
            __syncthreads();
            int d  = tid >> 2;
            int ns = (tid & 3) * 32;
            float bvv = bias[d];
            u32 hh[16];
#pragma unroll
            for (int j = 0; j < 32; j += 2) {
                float v0 = ot[d * 128 + ns + j] + bvv;
                float v1 = ot[d * 128 + ns + j + 1] + bvv;
                hh[j >> 1] = packbf(v0, v1);
            }
            size_t base = (size_t)(b * DIM + d) * HW + i0 + ns;
#pragma unroll
            for (int q4 = 0; q4 < 4; q4++)
                *(uint4*)&g_vth[base + q4 * 8] = *(uint4*)&hh[q4 * 4];
        }
    }
}

// ---------------------------------------------------------------------------
// Kernel 2: HMMA flash attention. 512 threads = 16 warps (8 M x 2 j-halves).
// Q fp16 register-resident; S single fp16 product; PV single bf16 product.
// Tile body reordered S0 -> exp0 -> S1 -> PV0 -> exp1 -> PV1 so exp MUFU
// overlaps independent tensor work.
// Smem: Q @0 (16K) | buf0 16K..48K (K 16K + V 16K) | buf1 48K..80K
// ---------------------------------------------------------------------------
#define ATT_BUF0   16384
#define ATT_BUFSZ  32768
#define SM_TOTAL   81920

__device__ __forceinline__ void load_kv(u32 sb, u32 bufbase, int b, int j0, int tid)
{
    const char* kh = (const char*)&g_k[(size_t)(b * HW + j0) * DIM];
#pragma unroll
    for (int i = 0; i < 2; i++) {
        int id = tid + i * 512, row = id >> 3, g = id & 7;
        CP16(sb + bufbase + swz128(row, g), kh + row * 128 + g * 16);
    }
    const char* vh = (const char*)&g_vth[(size_t)b * DIM * HW + j0];
#pragma unroll
    for (int i = 0; i < 2; i++) {
        int id = tid + i * 512, d = id >> 4, g = id & 15;
        CP16(sb + bufbase + 16384 + swz256(d, g), vh + d * (HW * 2) + g * 16);
    }
}

__global__ __launch_bounds__(512, 1) void attn_kernel()
{
    extern __shared__ char sm[];
    const u32 sb = smem_u32(sm);
    const int tid  = threadIdx.x;
    const int lane = tid & 31;
    const int wid  = tid >> 5;
    const int wm = wid & 7;
    const int wn = wid >> 3;
    const int b  = blockIdx.y;
    const int i0 = blockIdx.x * 128;
    const int g  = lane >> 2;
    const int t  = lane & 3;

    {
        const char* qh = (const char*)&g_q[(size_t)(b * HW + i0) * DIM];
#pragma unroll
        for (int i = 0; i < 2; i++) {
            int id = tid + i * 512, row = id >> 3, gg = id & 7;
            CP16(sb + swz128(row, gg), qh + row * 128 + gg * 16);
        }
        load_kv(sb, ATT_BUF0, b, 0, tid);
        CPC(); CPW0();
        __syncthreads();
    }

    u32 qf[4][4];
    {
        const u32 q_row  = wm * 16 + (lane & 15);
        const u32 q_gsel = (u32)(lane >> 4);
#pragma unroll
        for (int kt = 0; kt < 4; kt++)
            ldsm4(qf[kt], sb + swz128(q_row, q_gsel + kt * 2));
    }

    float oc[8][4];
    float lsum[2];
    lsum[0] = 0.0f; lsum[1] = 0.0f;
#pragma unroll
    for (int dnt = 0; dnt < 8; dnt++)
#pragma unroll
        for (int e = 0; e < 4; e++) oc[dnt][e] = 0.0f;

    const u32 b_ro = (u32)(((lane >> 4) << 3) + (lane & 7));
    const u32 b_gg = (u32)((lane >> 3) & 1);

    for (int jt = 0; jt < HW / 128; jt++) {
        CPW0();
        __syncthreads();
        const u32 buf = ATT_BUF0 + (u32)(jt & 1) * ATT_BUFSZ;
        if (jt + 1 < HW / 128)
            load_kv(sb, ATT_BUF0 + (u32)((jt + 1) & 1) * ATT_BUFSZ, b, (jt + 1) * 128, tid);
        CPC();

        float sc[4][4];
        u32 ph0[2][4], ph1[2][4];

        // ---- S half 0 ----
#pragma unroll
        for (int nt = 0; nt < 4; nt++)
#pragma unroll
            for (int e = 0; e < 4; e++) sc[nt][e] = 0.0f;
#pragma unroll
        for (int kt = 0; kt < 4; kt++)
#pragma unroll
            for (int ntp = 0; ntp < 2; ntp++) {
                u32 bh[4];
                u32 ro = (u32)(wn * 64 + ntp * 16) + b_ro;
                ldsm4(bh, sb + buf + swz128(ro, b_gg + kt * 2));
                mma16816h(sc[ntp * 2 + 0], qf[kt], bh + 0);
                mma16816h(sc[ntp * 2 + 1], qf[kt], bh + 2);
            }

        // ---- exp half 0 -> ph0 ----
#pragma unroll
        for (int jj = 0; jj < 2; jj++)
#pragma unroll
            for (int h = 0; h < 2; h++) {
                int nt = jj * 2 + h;
                float e0 = ex2f(sc[nt][0]);
                float e1 = ex2f(sc[nt][1]);
                float e2 = ex2f(sc[nt][2]);
                float e3 = ex2f(sc[nt][3]);
                lsum[0] += e0 + e1;
                lsum[1] += e2 + e3;
                ph0[jj][h * 2 + 0] = packbf(e0, e1);
                ph0[jj][h * 2 + 1] = packbf(e2, e3);
            }

        // ---- S half 1 (independent tensor work overlapping exp0) ----
#pragma unroll
        for (int nt = 0; nt < 4; nt++)
#pragma unroll
            for (int e = 0; e < 4; e++) sc[nt][e] = 0.0f;
#pragma unroll
        for (int kt = 0; kt < 4; kt++)
#pragma unroll
            for (int ntp = 0; ntp < 2; ntp++) {
                u32 bh[4];
                u32 ro = (u32)(wn * 64 + 32 + ntp * 16) + b_ro;
                ldsm4(bh, sb + buf + swz128(ro, b_gg + kt * 2));
                mma16816h(sc[ntp * 2 + 0], qf[kt], bh + 0);
                mma16816h(sc[ntp * 2 + 1], qf[kt], bh + 2);
            }

        // ---- PV half 0 ----
#pragma unroll
        for (int jj = 0; jj < 2; jj++) {
#pragma unroll
            for (int dntp = 0; dntp < 4; dntp++) {
                u32 bvh[4];
                u32 ro = (u32)(dntp * 16) + b_ro;
                u32 gg = (u32)(wn * 8 + jj * 2) + b_gg;
                ldsm4(bvh, sb + buf + 16384 + swz256(ro, gg));
                mma16816(oc[dntp * 2 + 0], ph0[jj], bvh + 0);
                mma16816(oc[dntp * 2 + 1], ph0[jj], bvh + 2);
            }
        }

        // ---- exp half 1 -> ph1 ----
#pragma unroll
        for (int jj = 0; jj < 2; jj++)
#pragma unroll
            for (int h = 0; h < 2; h++) {
                int nt = jj * 2 + h;
                float e0 = ex2f(sc[nt][0]);
                float e1 = ex2f(sc[nt][1]);
                float e2 = ex2f(sc[nt][2]);
                float e3 = ex2f(sc[nt][3]);
                lsum[0] += e0 + e1;
                lsum[1] += e2 + e3;
                ph1[jj][h * 2 + 0] = packbf(e0, e1);
                ph1[jj][h * 2 + 1] = packbf(e2, e3);
            }

        // ---- PV half 1 ----
#pragma unroll
        for (int jj = 0; jj < 2; jj++) {
#pragma unroll
            for (int dntp = 0; dntp < 4; dntp++) {
                u32 bvh[4];
                u32 ro = (u32)(dntp * 16) + b_ro;
                u32 gg = (u32)(wn * 8 + (2 + jj) * 2) + b_gg;
                ldsm4(bvh, sb + buf + 16384 + swz256(ro, gg));
                mma16816(oc[dntp * 2 + 0], ph1[jj], bvh + 0);
                mma16816(oc[dntp * 2 + 1], ph1[jj], bvh + 2);
            }
        }
    }
    __syncthreads();

    // ---- epilogue ----
    float* lp = (float*)(sm + 65536);
#pragma unroll
    for (int r = 0; r < 2; r++) {
        float v = lsum[r];
        v += __shfl_xor_sync(0xffffffffu, v, 1);
        v += __shfl_xor_sync(0xffffffffu, v, 2);
        if (t == 0) lp[wn * 128 + wm * 16 + r * 8 + g] = v;
    }
    float* op = (float*)(sm + wn * 32768);
#pragma unroll
    for (int dnt = 0; dnt < 8; dnt++) {
        int r0 = wm * 16 + g;
        int c = dnt * 8 + t * 2;
        *(float2*)&op[r0 * 64 + c]       = make_float2(oc[dnt][0], oc[dnt][1]);
        *(float2*)&op[(r0 + 8) * 64 + c] = make_float2(oc[dnt][2], oc[dnt][3]);
    }
    __syncthreads();

    float* o0 = (float*)sm;
    float* o1 = (float*)(sm + 32768);
    float* lpf = (float*)(sm + 65536);
#pragma unroll
    for (int i = 0; i < 4; i++) {
        int idx = tid + i * 512;
        int row = idx >> 4, c4 = (idx & 15) * 4;
        float invl = 1.0f / (lpf[row] + lpf[128 + row]);
        float4 a = *(float4*)&o0[row * 64 + c4];
        float4 bb = *(float4*)&o1[row * 64 + c4];
        float v0 = (a.x + bb.x) * invl;
        float v1 = (a.y + bb.y) * invl;
        float v2 = (a.z + bb.z) * invl;
        float v3 = (a.w + bb.w) * invl;
        size_t off = (size_t)(b * HW + i0 + row) * DIM + c4;
        *(uint2*)&g_sa[off] = make_uint2(packhf(v0, v1), packhf(v2, v3));
    }
}

// ---------------------------------------------------------------------------
// Kernel 3: output projection via single fp16 HMMA + bias + gamma + residual.
// ---------------------------------------------------------------------------
#define PROJ_SMEM 32768

__global__ __launch_bounds__(256, 2) void proj_mma_kernel(
    const float* __restrict__ x,
    const float* __restrict__ bsa,
    const float* __restrict__ gamma,
    float* __restrict__ out)
{
    extern __shared__ char sm[];
    const u32 sb = smem_u32(sm);
    const int tid  = threadIdx.x;
    const int lane = tid & 31;
    const int wid  = tid >> 5;
    const int wm = wid & 3;
    const int wn = wid >> 2;
    const int g  = lane >> 2;
    const int t  = lane & 3;
    const int b  = blockIdx.z;
    const int c0 = blockIdx.y * 128;
    const int n0 = blockIdx.x * 128;

    {
        const char* ah = (const char*)&g_wsa[(size_t)c0 * DIM];
        const char* bh = (const char*)&g_sa[(size_t)(b * HW + n0) * DIM];
#pragma unroll
        for (int i = 0; i < 4; i++) {
            int id = tid + i * 256;
            u32 row = (u32)(id >> 3), gg = (u32)(id & 7);
            u32 o = swz128(row, gg);
            u32 so = row * 128 + gg * 16;
            CP16(sb + o, ah + so);
            CP16(sb + 16384 + o, bh + so);
        }
        CPC(); CPW0();
        __syncthreads();
    }

    float c[2][8][4];
#pragma unroll
    for (int mt = 0; mt < 2; mt++)
#pragma unroll
        for (int nt = 0; nt < 8; nt++)
#pragma unroll
            for (int e = 0; e < 4; e++) c[mt][nt][e] = 0.0f;

    const u32 a_row = wm * 32 + (lane & 15);
    const u32 a_g = (u32)(lane >> 4);
    const u32 b_row = wn * 64 + (lane & 7);
    const u32 b_g = (u32)((lane >> 3) & 1);

#pragma unroll
    for (int kt = 0; kt < 4; kt++) {
        u32 ah2[2][4];
#pragma unroll
        for (int mt = 0; mt < 2; mt++)
            ldsm4(ah2[mt], sb + swz128(a_row + mt * 16, a_g + kt * 2));
#pragma unroll
        for (int nt = 0; nt < 8; nt++) {
            u32 bh2[2];
            ldsm2(bh2, sb + 16384 + swz128(b_row + nt * 8, b_g + kt * 2));
#pragma unroll
            for (int mt = 0; mt < 2; mt++)
                mma16816h(c[mt][nt], ah2[mt], bh2);
        }
    }

    const float gm = gamma[0];
#pragma unroll
    for (int mt = 0; mt < 2; mt++)
#pragma unroll
        for (int nt = 0; nt < 8; nt++) {
            int cg = c0 + wm * 32 + mt * 16 + g;
            int n  = n0 + wn * 64 + nt * 8 + t * 2;
            float b0 = bsa[cg], b1 = bsa[cg + 8];
            size_t off0 = ((size_t)(b * CIN) + cg) * HW + n;
            size_t off1 = off0 + (size_t)8 * HW;
            float2 xv0 = *(const float2*)&x[off0];
            float2 xv1 = *(const float2*)&x[off1];
            float2 o0, o1;
            o0.x = gm * (c[mt][nt][0] + b0) + xv0.x;
            o0.y = gm * (c[mt][nt][1] + b0) + xv0.y;
            o1.x = gm * (c[mt][nt][2] + b1) + xv1.x;
            o1.y = gm * (c[mt][nt][3] + b1) + xv1.y;
            *(float2*)&out[off0] = o0;
            *(float2*)&out[off1] = o1;
        }
}

// ---------------------------------------------------------------------------
extern "C" void kernel_launch(void* const* d_in, const int* in_sizes, int n_in,
                              void* d_out, int out_size)
{
    const float* x     = (const float*)d_in[0];
    const float* wq    = (const float*)d_in[1];
    const float* bq    = (const float*)d_in[2];
    const float* wk    = (const float*)d_in[3];
    const float* bk    = (const float*)d_in[4];
    const float* wv    = (const float*)d_in[5];
    const float* bv    = (const float*)d_in[6];
    const float* wsa   = (const float*)d_in[7];
    const float* bsa   = (const float*)d_in[8];
    const float* gamma = (const float*)d_in[9];
    float* out = (float*)d_out;

    cudaFuncSetAttribute(attn_kernel, cudaFuncAttributeMaxDynamicSharedMemorySize, SM_TOTAL);
    cudaFuncSetAttribute(qkv_fused_kernel, cudaFuncAttributeMaxDynamicSharedMemorySize, QF_SMEM);
    cudaFuncSetAttribute(proj_mma_kernel, cudaFuncAttributeMaxDynamicSharedMemorySize, PROJ_SMEM);

    convert_w_kernel<<<4, 256>>>(wq, wk, wv, wsa);
    qkv_fused_kernel<<<dim3(HW / 128, BATCH), 256, QF_SMEM>>>(x, bq, bk, bv);
    attn_kernel<<<dim3(HW / 128, BATCH), 512, SM_TOTAL>>>();
    proj_mma_kernel<<<dim3(HW / 128, CIN / 128, BATCH), 256, PROJ_SMEM>>>(x, bsa, gamma, out);
}

// round 15
// speedup vs baseline: 1.8020x; 1.0403x over previous
#include <cuda_runtime.h>
#include <cuda_bf16.h>
#include <cuda_fp16.h>
#include <math.h>
#include <stdint.h>
#include <string.h>

#define BATCH 4
#define CIN   256
#define HW    4096
#define DIM   64
#define LOG2E 1.4426950408889634f

typedef unsigned int u32;
typedef unsigned long long u64;

// ---------------------------------------------------------------------------
// Device scratch
// ---------------------------------------------------------------------------
__device__ __half g_w[3 * DIM * CIN];              // wq|wk|wv stacked [192][256]
__device__ __half g_wsa[CIN * DIM];
__device__ __half g_q[BATCH * HW * DIM];           // pre-scaled by log2(e)
__device__ __half g_k[BATCH * HW * DIM];
__device__ __nv_bfloat16 g_vth[BATCH * DIM * HW];  // [b][d][j] bf16
__device__ __half g_sa[BATCH * HW * DIM];          // attention out [b][n][d]

// ---------------------------------------------------------------------------
// Helpers
// ---------------------------------------------------------------------------
__device__ __forceinline__ uint32_t smem_u32(const void* p) {
    uint32_t a;
    asm("{ .reg .u64 t; cvta.to.shared.u64 t, %1; cvt.u32.u64 %0, t; }" : "=r"(a) : "l"(p));
    return a;
}
__device__ __forceinline__ u32 packbf(float lo, float hi) {
    u32 r;
    asm("cvt.rn.bf16x2.f32 %0, %1, %2;" : "=r"(r) : "f"(hi), "f"(lo));
    return r;
}
__device__ __forceinline__ u32 packhf(float lo, float hi) {
    u32 r;
    asm("cvt.rn.f16x2.f32 %0, %1, %2;" : "=r"(r) : "f"(hi), "f"(lo));
    return r;
}
__device__ __forceinline__ float ex2f(float x) {
    float r;
    asm("ex2.approx.f32 %0, %1;" : "=f"(r) : "f"(x));
    return r;
}
__device__ __forceinline__ void mma16816(float* c, const u32* a, const u32* b) {
    asm volatile(
        "mma.sync.aligned.m16n8k16.row.col.f32.bf16.bf16.f32 "
        "{%0,%1,%2,%3}, {%4,%5,%6,%7}, {%8,%9}, {%0,%1,%2,%3};"
        : "+f"(c[0]), "+f"(c[1]), "+f"(c[2]), "+f"(c[3])
        : "r"(a[0]), "r"(a[1]), "r"(a[2]), "r"(a[3]), "r"(b[0]), "r"(b[1]));
}
__device__ __forceinline__ void mma16816h(float* c, const u32* a, const u32* b) {
    asm volatile(
        "mma.sync.aligned.m16n8k16.row.col.f32.f16.f16.f32 "
        "{%0,%1,%2,%3}, {%4,%5,%6,%7}, {%8,%9}, {%0,%1,%2,%3};"
        : "+f"(c[0]), "+f"(c[1]), "+f"(c[2]), "+f"(c[3])
        : "r"(a[0]), "r"(a[1]), "r"(a[2]), "r"(a[3]), "r"(b[0]), "r"(b[1]));
}
__device__ __forceinline__ void ldsm4(u32* r, uint32_t addr) {
    asm volatile("ldmatrix.sync.aligned.m8n8.x4.shared.b16 {%0,%1,%2,%3}, [%4];"
        : "=r"(r[0]), "=r"(r[1]), "=r"(r[2]), "=r"(r[3]) : "r"(addr));
}
__device__ __forceinline__ void ldsm2(u32* r, uint32_t addr) {
    asm volatile("ldmatrix.sync.aligned.m8n8.x2.shared.b16 {%0,%1}, [%2];"
        : "=r"(r[0]), "=r"(r[1]) : "r"(addr));
}
#define CP16(dst, src) asm volatile("cp.async.cg.shared.global [%0], [%1], 16;" :: "r"(dst), "l"(src))
#define CPC()  asm volatile("cp.async.commit_group;")
#define CPW0() asm volatile("cp.async.wait_group 0;")

__device__ __forceinline__ u32 swz128(u32 row, u32 g) { return row * 128u + ((g ^ (row & 7u)) << 4); }
__device__ __forceinline__ u32 swz256(u32 row, u32 g) { return row * 256u + (((g & 8u) | ((g & 7u) ^ (row & 7u))) << 4); }
__device__ __forceinline__ u32 swz512(u32 row, u32 g) { return row * 512u + (((g & 24u) | ((g & 7u) ^ (row & 7u))) << 4); }

// ---------------------------------------------------------------------------
// Kernel 0: weight conversion -> fp16 (parallelized: 32 blocks)
// ---------------------------------------------------------------------------
__global__ void convert_w_kernel(const float* __restrict__ wq, const float* __restrict__ wk,
                                 const float* __restrict__ wv, const float* __restrict__ wsa)
{
    const int p = blockIdx.x & 3;
    const int s8 = blockIdx.x >> 2;     // slice 0..7
    const float* s = (p == 0) ? wq : (p == 1) ? wk : (p == 2) ? wv : wsa;
    __half* d = (p < 3) ? &g_w[p * DIM * CIN] : g_wsa;
    const int per = DIM * CIN / 8;      // 2048
    for (int i = threadIdx.x; i < per; i += blockDim.x) {
        int idx = s8 * per + i;
        d[idx] = __float2half(s[idx]);
    }
}

// ---------------------------------------------------------------------------
// Kernel 1: FUSED x-transpose + QKV projections (fp16 HMMA).
// ---------------------------------------------------------------------------
#define QF_A   0
#define QF_B   65536
#define QF_XS  163840
#define QF_SMEM 197632
#define XS_STRIDE 132

__global__ __launch_bounds__(256, 1) void qkv_fused_kernel(
    const float* __restrict__ x,
    const float* __restrict__ bq, const float* __restrict__ bk, const float* __restrict__ bv)
{
    extern __shared__ char sm[];
    const u32 sb = smem_u32(sm);
    const int tid  = threadIdx.x;
    const int lane = tid & 31;
    const int wid  = tid >> 5;
    const int wm = wid & 3;
    const int wn = wid >> 2;
    const int g  = lane >> 2;
    const int t  = lane & 3;
    const int b  = blockIdx.y;
    const int i0 = blockIdx.x * 128;

#pragma unroll
    for (int i = 0; i < 24; i++) {
        int id = tid + i * 256;
        u32 row = (u32)(id >> 5), gg = (u32)(id & 31);
        CP16(sb + QF_B + swz512(row, gg), (const char*)g_w + row * 512 + gg * 16);
    }
    CPC();

    float* xs = (float*)(sm + QF_XS);
    const int tn  = (lane) + ((tid >> 5) & 3) * 32;
    const int glh = (tid >> 7) * 4;
    for (int kc = 0; kc < 4; kc++) {
        CPW0();
        __syncthreads();
#pragma unroll
        for (int i = 0; i < 8; i++) {
            int id = tid + i * 256;
            int r = id >> 5, gg = id & 31;
            CP16(sb + QF_XS + r * (XS_STRIDE * 4) + gg * 16,
                 (const char*)&x[(size_t)(b * CIN + kc * 64 + r) * HW + i0] + gg * 16);
        }
        CPC(); CPW0();
        __syncthreads();
#pragma unroll
        for (int gi = 0; gi < 4; gi++) {
            int gl = glh + gi;
            u32 w4[4];
#pragma unroll
            for (int s = 0; s < 4; s++) {
                float f0 = xs[(gl * 8 + 2 * s)     * XS_STRIDE + tn];
                float f1 = xs[(gl * 8 + 2 * s + 1) * XS_STRIDE + tn];
                w4[s] = packhf(f0, f1);
            }
            *(uint4*)(sm + QF_A + swz512((u32)tn, (u32)(kc * 8 + gl))) = *(uint4*)w4;
        }
    }
    __syncthreads();

    const u32 a_row = wm * 32 + (lane & 15);
    const u32 a_g = (u32)(lane >> 4);
    const u32 b_rl = (u32)(lane & 7);
    const u32 b_g = (u32)((lane >> 3) & 1);

    for (int p = 0; p < 3; p++) {
        const float* bias = (p == 0) ? bq : (p == 1) ? bk : bv;
        const float scl = (p == 0) ? LOG2E : 1.0f;

        float c[2][4][4];
#pragma unroll
        for (int mt = 0; mt < 2; mt++)
#pragma unroll
            for (int nt = 0; nt < 4; nt++)
#pragma unroll
                for (int e = 0; e < 4; e++) c[mt][nt][e] = 0.0f;

#pragma unroll
        for (int kt = 0; kt < 16; kt++) {
            u32 ah2[2][4];
#pragma unroll
            for (int mt = 0; mt < 2; mt++)
                ldsm4(ah2[mt], sb + QF_A + swz512(a_row + mt * 16, a_g + kt * 2));
#pragma unroll
            for (int nt = 0; nt < 4; nt++) {
                u32 bh2[2];
                u32 row = (u32)(p * 64 + wn * 32 + nt * 8) + b_rl;
                ldsm2(bh2, sb + QF_B + swz512(row, b_g + kt * 2));
#pragma unroll
                for (int mt = 0; mt < 2; mt++)
                    mma16816h(c[mt][nt], ah2[mt], bh2);
            }
        }

        if (p < 2) {
            __half* oh = (p == 0) ? g_q : g_k;
#pragma unroll
            for (int mt = 0; mt < 2; mt++)
#pragma unroll
                for (int nt = 0; nt < 4; nt++) {
                    int n = i0 + wm * 32 + mt * 16 + g;
                    int d = wn * 32 + nt * 8 + t * 2;
                    float b0 = bias[d], b1 = bias[d + 1];
                    float v0 = (c[mt][nt][0] + b0) * scl, v1 = (c[mt][nt][1] + b1) * scl;
                    float v2 = (c[mt][nt][2] + b0) * scl, v3 = (c[mt][nt][3] + b1) * scl;
                    size_t o0 = (size_t)(b * HW + n) * DIM + d;
                    size_t o1 = (size_t)(b * HW + n + 8) * DIM + d;
                    *(u32*)&oh[o0] = packhf(v0, v1);
                    *(u32*)&oh[o1] = packhf(v2, v3);
                }
        } else {
            float* ot = (float*)(sm + QF_XS);
            __syncthreads();
#pragma unroll
            for (int mt = 0; mt < 2; mt++)
#pragma unroll
                for (int nt = 0; nt < 4; nt++) {
                    int n = wm * 32 + mt * 16 + g;
                    int d = wn * 32 + nt * 8 + t * 2;
                    ot[d * 128 + n]           = c[mt][nt][0];
                    ot[(d + 1) * 128 + n]     = c[mt][nt][1];
                    ot[d * 128 + n + 8]       = c[mt][nt][2];
                    ot[(d + 1) * 128 + n + 8] = c[mt][nt][3];
                }
            __syncthreads();
            int d  = tid >> 2;
            int ns = (tid & 3) * 32;
            float bvv = bias[d];
            u32 hh[16];
#pragma unroll
            for (int j = 0; j < 32; j += 2) {
                float v0 = ot[d * 128 + ns + j] + bvv;
                float v1 = ot[d * 128 + ns + j + 1] + bvv;
                hh[j >> 1] = packbf(v0, v1);
            }
            size_t base = (size_t)(b * DIM + d) * HW + i0 + ns;
#pragma unroll
            for (int q4 = 0; q4 < 4; q4++)
                *(uint4*)&g_vth[base + q4 * 8] = *(uint4*)&hh[q4 * 4];
        }
    }
}

// ---------------------------------------------------------------------------
// Kernel 2: HMMA flash attention (unchanged from R14 mainloop).
// ---------------------------------------------------------------------------
#define ATT_BUF0   16384
#define ATT_BUFSZ  32768
#define SM_TOTAL   81920

__device__ __forceinline__ void load_kv(u32 sb, u32 bufbase, int b, int j0, int tid)
{
    const char* kh = (const char*)&g_k[(size_t)(b * HW + j0) * DIM];
#pragma unroll
    for (int i = 0; i < 2; i++) {
        int id = tid + i * 512, row = id >> 3, g = id & 7;
        CP16(sb + bufbase + swz128(row, g), kh + row * 128 + g * 16);
    }
    const char* vh = (const char*)&g_vth[(size_t)b * DIM * HW + j0];
#pragma unroll
    for (int i = 0; i < 2; i++) {
        int id = tid + i * 512, d = id >> 4, g = id & 15;
        CP16(sb + bufbase + 16384 + swz256(d, g), vh + d * (HW * 2) + g * 16);
    }
}

__global__ __launch_bounds__(512, 1) void attn_kernel()
{
    extern __shared__ char sm[];
    const u32 sb = smem_u32(sm);
    const int tid  = threadIdx.x;
    const int lane = tid & 31;
    const int wid  = tid >> 5;
    const int wm = wid & 7;
    const int wn = wid >> 3;
    const int b  = blockIdx.y;
    const int i0 = blockIdx.x * 128;
    const int g  = lane >> 2;
    const int t  = lane & 3;

    {
        const char* qh = (const char*)&g_q[(size_t)(b * HW + i0) * DIM];
#pragma unroll
        for (int i = 0; i < 2; i++) {
            int id = tid + i * 512, row = id >> 3, gg = id & 7;
            CP16(sb + swz128(row, gg), qh + row * 128 + gg * 16);
        }
        load_kv(sb, ATT_BUF0, b, 0, tid);
        CPC(); CPW0();
        __syncthreads();
    }

    u32 qf[4][4];
    {
        const u32 q_row  = wm * 16 + (lane & 15);
        const u32 q_gsel = (u32)(lane >> 4);
#pragma unroll
        for (int kt = 0; kt < 4; kt++)
            ldsm4(qf[kt], sb + swz128(q_row, q_gsel + kt * 2));
    }

    float oc[8][4];
    float lsum[2];
    lsum[0] = 0.0f; lsum[1] = 0.0f;
#pragma unroll
    for (int dnt = 0; dnt < 8; dnt++)
#pragma unroll
        for (int e = 0; e < 4; e++) oc[dnt][e] = 0.0f;

    const u32 b_ro = (u32)(((lane >> 4) << 3) + (lane & 7));
    const u32 b_gg = (u32)((lane >> 3) & 1);

    for (int jt = 0; jt < HW / 128; jt++) {
        CPW0();
        __syncthreads();
        const u32 buf = ATT_BUF0 + (u32)(jt & 1) * ATT_BUFSZ;
        if (jt + 1 < HW / 128)
            load_kv(sb, ATT_BUF0 + (u32)((jt + 1) & 1) * ATT_BUFSZ, b, (jt + 1) * 128, tid);
        CPC();

        float sc[4][4];
        u32 ph0[2][4], ph1[2][4];

#pragma unroll
        for (int nt = 0; nt < 4; nt++)
#pragma unroll
            for (int e = 0; e < 4; e++) sc[nt][e] = 0.0f;
#pragma unroll
        for (int kt = 0; kt < 4; kt++)
#pragma unroll
            for (int ntp = 0; ntp < 2; ntp++) {
                u32 bh[4];
                u32 ro = (u32)(wn * 64 + ntp * 16) + b_ro;
                ldsm4(bh, sb + buf + swz128(ro, b_gg + kt * 2));
                mma16816h(sc[ntp * 2 + 0], qf[kt], bh + 0);
                mma16816h(sc[ntp * 2 + 1], qf[kt], bh + 2);
            }

#pragma unroll
        for (int jj = 0; jj < 2; jj++)
#pragma unroll
            for (int h = 0; h < 2; h++) {
                int nt = jj * 2 + h;
                float e0 = ex2f(sc[nt][0]);
                float e1 = ex2f(sc[nt][1]);
                float e2 = ex2f(sc[nt][2]);
                float e3 = ex2f(sc[nt][3]);
                lsum[0] += e0 + e1;
                lsum[1] += e2 + e3;
                ph0[jj][h * 2 + 0] = packbf(e0, e1);
                ph0[jj][h * 2 + 1] = packbf(e2, e3);
            }

#pragma unroll
        for (int nt = 0; nt < 4; nt++)
#pragma unroll
            for (int e = 0; e < 4; e++) sc[nt][e] = 0.0f;
#pragma unroll
        for (int kt = 0; kt < 4; kt++)
#pragma unroll
            for (int ntp = 0; ntp < 2; ntp++) {
                u32 bh[4];
                u32 ro = (u32)(wn * 64 + 32 + ntp * 16) + b_ro;
                ldsm4(bh, sb + buf + swz128(ro, b_gg + kt * 2));
                mma16816h(sc[ntp * 2 + 0], qf[kt], bh + 0);
                mma16816h(sc[ntp * 2 + 1], qf[kt], bh + 2);
            }

#pragma unroll
        for (int jj = 0; jj < 2; jj++) {
#pragma unroll
            for (int dntp = 0; dntp < 4; dntp++) {
                u32 bvh[4];
                u32 ro = (u32)(dntp * 16) + b_ro;
                u32 gg = (u32)(wn * 8 + jj * 2) + b_gg;
                ldsm4(bvh, sb + buf + 16384 + swz256(ro, gg));
                mma16816(oc[dntp * 2 + 0], ph0[jj], bvh + 0);
                mma16816(oc[dntp * 2 + 1], ph0[jj], bvh + 2);
            }
        }

#pragma unroll
        for (int jj = 0; jj < 2; jj++)
#pragma unroll
            for (int h = 0; h < 2; h++) {
                int nt = jj * 2 + h;
                float e0 = ex2f(sc[nt][0]);
                float e1 = ex2f(sc[nt][1]);
                float e2 = ex2f(sc[nt][2]);
                float e3 = ex2f(sc[nt][3]);
                lsum[0] += e0 + e1;
                lsum[1] += e2 + e3;
                ph1[jj][h * 2 + 0] = packbf(e0, e1);
                ph1[jj][h * 2 + 1] = packbf(e2, e3);
            }

#pragma unroll
        for (int jj = 0; jj < 2; jj++) {
#pragma unroll
            for (int dntp = 0; dntp < 4; dntp++) {
                u32 bvh[4];
                u32 ro = (u32)(dntp * 16) + b_ro;
                u32 gg = (u32)(wn * 8 + (2 + jj) * 2) + b_gg;
                ldsm4(bvh, sb + buf + 16384 + swz256(ro, gg));
                mma16816(oc[dntp * 2 + 0], ph1[jj], bvh + 0);
                mma16816(oc[dntp * 2 + 1], ph1[jj], bvh + 2);
            }
        }
    }
    __syncthreads();

    float* lp = (float*)(sm + 65536);
#pragma unroll
    for (int r = 0; r < 2; r++) {
        float v = lsum[r];
        v += __shfl_xor_sync(0xffffffffu, v, 1);
        v += __shfl_xor_sync(0xffffffffu, v, 2);
        if (t == 0) lp[wn * 128 + wm * 16 + r * 8 + g] = v;
    }
    float* op = (float*)(sm + wn * 32768);
#pragma unroll
    for (int dnt = 0; dnt < 8; dnt++) {
        int r0 = wm * 16 + g;
        int c = dnt * 8 + t * 2;
        *(float2*)&op[r0 * 64 + c]       = make_float2(oc[dnt][0], oc[dnt][1]);
        *(float2*)&op[(r0 + 8) * 64 + c] = make_float2(oc[dnt][2], oc[dnt][3]);
    }
    __syncthreads();

    float* o0 = (float*)sm;
    float* o1 = (float*)(sm + 32768);
    float* lpf = (float*)(sm + 65536);
#pragma unroll
    for (int i = 0; i < 4; i++) {
        int idx = tid + i * 512;
        int row = idx >> 4, c4 = (idx & 15) * 4;
        float invl = 1.0f / (lpf[row] + lpf[128 + row]);
        float4 a = *(float4*)&o0[row * 64 + c4];
        float4 bb = *(float4*)&o1[row * 64 + c4];
        float v0 = (a.x + bb.x) * invl;
        float v1 = (a.y + bb.y) * invl;
        float v2 = (a.z + bb.z) * invl;
        float v3 = (a.w + bb.w) * invl;
        size_t off = (size_t)(b * HW + i0 + row) * DIM + c4;
        *(uint2*)&g_sa[off] = make_uint2(packhf(v0, v1), packhf(v2, v3));
    }
}

// ---------------------------------------------------------------------------
// Kernel 3: output projection. Re-tiled M=64(c) x N=128(n) x K=64 for high
// CTA-level parallelism (512 CTAs, 24KB smem -> 4+ CTAs/SM) since this
// kernel is memory-latency bound.
// Smem: A(wsa) @0 (8K) | B(sa) @8K (16K) = 24K.
// ---------------------------------------------------------------------------
#define PROJ_SMEM 24576

__global__ __launch_bounds__(256) void proj_mma_kernel(
    const float* __restrict__ x,
    const float* __restrict__ bsa,
    const float* __restrict__ gamma,
    float* __restrict__ out)
{
    extern __shared__ char sm[];
    const u32 sb = smem_u32(sm);
    const int tid  = threadIdx.x;
    const int lane = tid & 31;
    const int wid  = tid >> 5;
    const int wm = wid & 3;      // c group: rows wm*16 .. +15
    const int wn = wid >> 2;     // n half:  cols wn*64 .. +63
    const int g  = lane >> 2;
    const int t  = lane & 3;
    const int b  = blockIdx.z;
    const int c0 = blockIdx.y * 64;
    const int n0 = blockIdx.x * 128;

    {
        const char* ah = (const char*)&g_wsa[(size_t)c0 * DIM];
        const char* bh = (const char*)&g_sa[(size_t)(b * HW + n0) * DIM];
        // A: 64 rows x 128B = 512 granules; B: 128 rows = 1024 granules
#pragma unroll
        for (int i = 0; i < 2; i++) {
            int id = tid + i * 256;
            u32 row = (u32)(id >> 3), gg = (u32)(id & 7);
            CP16(sb + swz128(row, gg), ah + row * 128 + gg * 16);
        }
#pragma unroll
        for (int i = 0; i < 4; i++) {
            int id = tid + i * 256;
            u32 row = (u32)(id >> 3), gg = (u32)(id & 7);
            CP16(sb + 8192 + swz128(row, gg), bh + row * 128 + gg * 16);
        }
        CPC(); CPW0();
        __syncthreads();
    }

    float c[8][4];
#pragma unroll
    for (int nt = 0; nt < 8; nt++)
#pragma unroll
        for (int e = 0; e < 4; e++) c[nt][e] = 0.0f;

    const u32 a_row = wm * 16 + (lane & 15);
    const u32 a_g = (u32)(lane >> 4);
    const u32 b_row = wn * 64 + (lane & 7);
    const u32 b_g = (u32)((lane >> 3) & 1);

#pragma unroll
    for (int kt = 0; kt < 4; kt++) {
        u32 ah2[4];
        ldsm4(ah2, sb + swz128(a_row, a_g + kt * 2));
#pragma unroll
        for (int nt = 0; nt < 8; nt++) {
            u32 bh2[2];
            ldsm2(bh2, sb + 8192 + swz128(b_row + nt * 8, b_g + kt * 2));
            mma16816h(c[nt], ah2, bh2);
        }
    }

    const float gm = gamma[0];
#pragma unroll
    for (int nt = 0; nt < 8; nt++) {
        int cg = c0 + wm * 16 + g;
        int n  = n0 + wn * 64 + nt * 8 + t * 2;
        float b0 = bsa[cg], b1 = bsa[cg + 8];
        size_t off0 = ((size_t)(b * CIN) + cg) * HW + n;
        size_t off1 = off0 + (size_t)8 * HW;
        float2 xv0 = *(const float2*)&x[off0];
        float2 xv1 = *(const float2*)&x[off1];
        float2 o0, o1;
        o0.x = gm * (c[nt][0] + b0) + xv0.x;
        o0.y = gm * (c[nt][1] + b0) + xv0.y;
        o1.x = gm * (c[nt][2] + b1) + xv1.x;
        o1.y = gm * (c[nt][3] + b1) + xv1.y;
        *(float2*)&out[off0] = o0;
        *(float2*)&out[off1] = o1;
    }
}

// ---------------------------------------------------------------------------
extern "C" void kernel_launch(void* const* d_in, const int* in_sizes, int n_in,
                              void* d_out, int out_size)
{
    const float* x     = (const float*)d_in[0];
    const float* wq    = (const float*)d_in[1];
    const float* bq    = (const float*)d_in[2];
    const float* wk    = (const float*)d_in[3];
    const float* bk    = (const float*)d_in[4];
    const float* wv    = (const float*)d_in[5];
    const float* bv    = (const float*)d_in[6];
    const float* wsa   = (const float*)d_in[7];
    const float* bsa   = (const float*)d_in[8];
    const float* gamma = (const float*)d_in[9];
    float* out = (float*)d_out;

    cudaFuncSetAttribute(attn_kernel, cudaFuncAttributeMaxDynamicSharedMemorySize, SM_TOTAL);
    cudaFuncSetAttribute(qkv_fused_kernel, cudaFuncAttributeMaxDynamicSharedMemorySize, QF_SMEM);
    cudaFuncSetAttribute(proj_mma_kernel, cudaFuncAttributeMaxDynamicSharedMemorySize, PROJ_SMEM);

    convert_w_kernel<<<32, 256>>>(wq, wk, wv, wsa);
    qkv_fused_kernel<<<dim3(HW / 128, BATCH), 256, QF_SMEM>>>(x, bq, bk, bv);
    attn_kernel<<<dim3(HW / 128, BATCH), 512, SM_TOTAL>>>();
    proj_mma_kernel<<<dim3(HW / 128, CIN / 64, BATCH), 256, PROJ_SMEM>>>(x, bsa, gamma, out);
}